// round 3
// baseline (speedup 1.0000x reference)
#include <cuda_runtime.h>
#include <cuda_bf16.h>
#include <cstdint>

#define N_NODES 50000
#define N_EDGES 1600000
#define N_GRAPHS 64

// ---------------- scratch (device globals; no allocations allowed) ----------
__device__ int   g_deg[N_NODES];
__device__ int   g_off[N_NODES + 1];
__device__ int   g_cursor[N_NODES];
__device__ float g_deginv[N_NODES];
__device__ int   g_srcs[N_EDGES];          // src ids sorted by dst
__device__ int   g_partials[512];          // chunk sums for scan

__device__ float g_agg[(size_t)N_NODES * 256];
__device__ float g_h1 [(size_t)N_NODES * 256];
__device__ float g_h2 [(size_t)N_NODES * 256];
__device__ float g_h3 [(size_t)N_NODES * 128];

#define SCAN_CHUNK 128
#define N_CHUNKS ((N_NODES + SCAN_CHUNK - 1) / SCAN_CHUNK)   // 391

// buffer selectors (device-side resolution of __device__ globals)
__device__ __forceinline__ const float* sel_buf(int sel, const float* x) {
    switch (sel) {
        case 0: return x;
        case 1: return g_h1;
        case 2: return g_h2;
        default: return g_agg;
    }
}
__device__ __forceinline__ float* sel_out(int sel) {
    switch (sel) {
        case 1: return g_h1;
        case 2: return g_h2;
        default: return g_h3;
    }
}

// ---------------- preprocessing: counting sort of edges by dst --------------
__global__ void k_zero_deg() {
    int i = blockIdx.x * blockDim.x + threadIdx.x;
    if (i < N_NODES) g_deg[i] = 0;
}

__global__ void k_count(const int* __restrict__ ei) {
    int i = blockIdx.x * blockDim.x + threadIdx.x;
    if (i >= N_EDGES) return;
    int d = ei[N_EDGES + i];
    atomicAdd(&g_deg[d], 1);
}

__global__ void k_chunk_sums() {
    __shared__ int s[SCAN_CHUNK];
    int base = blockIdx.x * SCAN_CHUNK;
    int i = base + threadIdx.x;
    s[threadIdx.x] = (i < N_NODES) ? g_deg[i] : 0;
    __syncthreads();
    for (int stride = SCAN_CHUNK / 2; stride > 0; stride >>= 1) {
        if (threadIdx.x < stride) s[threadIdx.x] += s[threadIdx.x + stride];
        __syncthreads();
    }
    if (threadIdx.x == 0) g_partials[blockIdx.x] = s[0];
}

__global__ void k_scan_partials() {
    __shared__ int s[512];
    int t = threadIdx.x;
    s[t] = (t < N_CHUNKS) ? g_partials[t] : 0;
    __syncthreads();
    if (t == 0) {
        int run = 0;
        for (int i = 0; i < N_CHUNKS; ++i) { int v = s[i]; s[i] = run; run += v; }
        g_off[N_NODES] = N_EDGES;
    }
    __syncthreads();
    if (t < N_CHUNKS) g_partials[t] = s[t];
}

__global__ void k_scan_chunks() {
    __shared__ int sd[SCAN_CHUNK];
    __shared__ int so[SCAN_CHUNK];
    int base = blockIdx.x * SCAN_CHUNK;
    int i = base + threadIdx.x;
    int d = (i < N_NODES) ? g_deg[i] : 0;
    sd[threadIdx.x] = d;
    __syncthreads();
    if (threadIdx.x == 0) {
        int run = g_partials[blockIdx.x];
        #pragma unroll 4
        for (int k = 0; k < SCAN_CHUNK; ++k) { so[k] = run; run += sd[k]; }
    }
    __syncthreads();
    if (i < N_NODES) {
        int o = so[threadIdx.x];
        g_off[i] = o;
        g_cursor[i] = o;
        g_deginv[i] = (d > 0) ? (1.0f / (float)d) : 0.0f;
    }
}

__global__ void k_fill(const int* __restrict__ ei) {
    int i = blockIdx.x * blockDim.x + threadIdx.x;
    if (i >= N_EDGES) return;
    int s = ei[i];
    int d = ei[N_EDGES + i];
    int pos = atomicAdd(&g_cursor[d], 1);
    g_srcs[pos] = s;
}

// ---------------- aggregation: warp per node, float4 gather -----------------
// NV4: float4 per lane (K=128 -> 1, K=256 -> 2); SRCSEL picks input buffer.
// Output always g_agg.
template <int NV4, int SRCSEL>
__global__ void k_aggregate(const float* __restrict__ xext) {
    int w = (blockIdx.x * blockDim.x + threadIdx.x) >> 5;
    if (w >= N_NODES) return;
    const float* __restrict__ X = sel_buf(SRCSEL, xext);
    int lane = threadIdx.x & 31;
    int beg = g_off[w];
    int end = g_off[w + 1];
    float inv = g_deginv[w];
    const float4* X4 = (const float4*)X;
    const int RV = NV4 * 32;   // float4 per row

    float4 acc0[NV4], acc1[NV4];
    #pragma unroll
    for (int v = 0; v < NV4; ++v) {
        acc0[v] = make_float4(0.f, 0.f, 0.f, 0.f);
        acc1[v] = make_float4(0.f, 0.f, 0.f, 0.f);
    }

    int j = beg;
    for (; j + 2 <= end; j += 2) {
        int s0 = g_srcs[j], s1 = g_srcs[j + 1];
        #pragma unroll
        for (int v = 0; v < NV4; ++v) {
            float4 a = X4[(size_t)s0 * RV + v * 32 + lane];
            float4 b = X4[(size_t)s1 * RV + v * 32 + lane];
            acc0[v].x += a.x; acc0[v].y += a.y; acc0[v].z += a.z; acc0[v].w += a.w;
            acc1[v].x += b.x; acc1[v].y += b.y; acc1[v].z += b.z; acc1[v].w += b.w;
        }
    }
    if (j < end) {
        int s0 = g_srcs[j];
        #pragma unroll
        for (int v = 0; v < NV4; ++v) {
            float4 a = X4[(size_t)s0 * RV + v * 32 + lane];
            acc0[v].x += a.x; acc0[v].y += a.y; acc0[v].z += a.z; acc0[v].w += a.w;
        }
    }

    float4* O4 = (float4*)g_agg;
    #pragma unroll
    for (int v = 0; v < NV4; ++v) {
        float4 r;
        r.x = (acc0[v].x + acc1[v].x) * inv;
        r.y = (acc0[v].y + acc1[v].y) * inv;
        r.z = (acc0[v].z + acc1[v].z) * inv;
        r.w = (acc0[v].w + acc1[v].w) * inv;
        O4[(size_t)w * RV + v * 32 + lane] = r;
    }
}

// ---------------- dual-A SGEMM + bias + relu --------------------------------
// C[m][n] = relu( sum_k A1[m][k]*B1[n][k] + sum_k A2[m][k]*B2[n][k] + bias[n] )
// A1 = g_agg. A2 = sel_buf(A2SEL, xext). C = sel_out(CSEL).
#define BM 128
#define BN 64
#define BK 16

template <int A2SEL, int CSEL>
__global__ __launch_bounds__(256)
void k_gemm_dual_relu(const float* __restrict__ xext,
                      const float* __restrict__ B1, const float* __restrict__ B2,
                      const float* __restrict__ bias,
                      int M, int N, int K) {
    __shared__ float As[BK][BM + 4];
    __shared__ float Bs[BK][BN + 4];

    const float* __restrict__ A1 = g_agg;
    const float* __restrict__ A2 = sel_buf(A2SEL, xext);
    float* __restrict__ C = sel_out(CSEL);

    int bm = blockIdx.x * BM;
    int bn = blockIdx.y * BN;
    int t  = threadIdx.x;          // 256
    int tx = t & 15;               // n-dir: 16 threads * 4 cols
    int ty = t >> 4;               // m-dir: 16 threads * 8 rows

    float acc[8][4];
    #pragma unroll
    for (int i = 0; i < 8; ++i)
        #pragma unroll
        for (int j = 0; j < 4; ++j) acc[i][j] = 0.f;

    #pragma unroll
    for (int mat = 0; mat < 2; ++mat) {
        const float* A = mat ? A2 : A1;
        const float* B = mat ? B2 : B1;
        for (int k0 = 0; k0 < K; k0 += BK) {
            // A tile: 128 x 16 = 512 float4, 2 per thread (stored transposed)
            #pragma unroll
            for (int i = 0; i < 2; ++i) {
                int idx = t + i * 256;
                int row = idx >> 2;
                int kq  = idx & 3;
                int gm  = bm + row;
                float4 v = make_float4(0.f, 0.f, 0.f, 0.f);
                if (gm < M) v = *(const float4*)(A + (size_t)gm * K + k0 + kq * 4);
                As[kq * 4 + 0][row] = v.x;
                As[kq * 4 + 1][row] = v.y;
                As[kq * 4 + 2][row] = v.z;
                As[kq * 4 + 3][row] = v.w;
            }
            // B tile: 64 x 16 = 256 float4, 1 per thread (stored transposed)
            {
                int row = t >> 2;
                int kq  = t & 3;
                float4 v = *(const float4*)(B + (size_t)(bn + row) * K + k0 + kq * 4);
                Bs[kq * 4 + 0][row] = v.x;
                Bs[kq * 4 + 1][row] = v.y;
                Bs[kq * 4 + 2][row] = v.z;
                Bs[kq * 4 + 3][row] = v.w;
            }
            __syncthreads();

            #pragma unroll
            for (int kk = 0; kk < BK; ++kk) {
                float4 a0 = *(const float4*)&As[kk][ty * 8];
                float4 a1 = *(const float4*)&As[kk][ty * 8 + 4];
                float4 bv = *(const float4*)&Bs[kk][tx * 4];
                float a[8] = {a0.x, a0.y, a0.z, a0.w, a1.x, a1.y, a1.z, a1.w};
                float b[4] = {bv.x, bv.y, bv.z, bv.w};
                #pragma unroll
                for (int i = 0; i < 8; ++i)
                    #pragma unroll
                    for (int j = 0; j < 4; ++j)
                        acc[i][j] += a[i] * b[j];
            }
            __syncthreads();
        }
    }

    float4 bv = *(const float4*)(bias + bn + tx * 4);
    #pragma unroll
    for (int i = 0; i < 8; ++i) {
        int gm = bm + ty * 8 + i;
        if (gm < M) {
            float4 o;
            o.x = fmaxf(acc[i][0] + bv.x, 0.f);
            o.y = fmaxf(acc[i][1] + bv.y, 0.f);
            o.z = fmaxf(acc[i][2] + bv.z, 0.f);
            o.w = fmaxf(acc[i][3] + bv.w, 0.f);
            *(float4*)(C + (size_t)gm * N + bn + tx * 4) = o;
        }
    }
}

// ---------------- global add pool -------------------------------------------
__global__ void k_zero_out(float* out, int n) {
    int i = blockIdx.x * blockDim.x + threadIdx.x;
    if (i < n) out[i] = 0.f;
}

__global__ void k_pool(const int* __restrict__ batch, float* __restrict__ out) {
    int idx = blockIdx.x * blockDim.x + threadIdx.x;    // node*32 + q
    if (idx >= N_NODES * 32) return;
    int node = idx >> 5;
    int q    = idx & 31;
    int g    = batch[node];
    float4 v = ((const float4*)g_h3)[(size_t)node * 32 + q];
    float* p = out + (size_t)g * 128 + q * 4;
    atomicAdd(p + 0, v.x);
    atomicAdd(p + 1, v.y);
    atomicAdd(p + 2, v.z);
    atomicAdd(p + 3, v.w);
}

// ---------------- launch ----------------------------------------------------
extern "C" void kernel_launch(void* const* d_in, const int* in_sizes, int n_in,
                              void* d_out, int out_size) {
    const float* x     = (const float*)d_in[0];
    const int*   ei    = (const int*)d_in[1];     // int32! (JAX default x64-disabled)
    const int*   batch = (const int*)d_in[2];     // int32!
    const float* W1l = (const float*)d_in[3];
    const float* b1  = (const float*)d_in[4];
    const float* W1r = (const float*)d_in[5];
    const float* W2l = (const float*)d_in[6];
    const float* b2  = (const float*)d_in[7];
    const float* W2r = (const float*)d_in[8];
    const float* W3l = (const float*)d_in[9];
    const float* b3  = (const float*)d_in[10];
    const float* W3r = (const float*)d_in[11];
    float* out = (float*)d_out;

    const int EB = (N_EDGES + 255) / 256;          // 6250
    const int NB = (N_NODES + 255) / 256;          // 196
    const int AGGB = (N_NODES * 32 + 255) / 256;   // warp per node: 6250

    // preprocessing: counting sort of edges by dst
    k_zero_deg<<<NB, 256>>>();
    k_count<<<EB, 256>>>(ei);
    k_chunk_sums<<<N_CHUNKS, SCAN_CHUNK>>>();
    k_scan_partials<<<1, 512>>>();
    k_scan_chunks<<<N_CHUNKS, SCAN_CHUNK>>>();
    k_fill<<<EB, 256>>>(ei);

    dim3 g1((N_NODES + BM - 1) / BM, 256 / BN);    // 391 x 4
    dim3 g3((N_NODES + BM - 1) / BM, 128 / BN);    // 391 x 2

    // layer 1: K=128 -> 256   (agg(x) @ W1l^T + x @ W1r^T -> g_h1)
    k_aggregate<1, 0><<<AGGB, 256>>>(x);
    k_gemm_dual_relu<0, 1><<<g1, 256>>>(x, W1l, W1r, b1, N_NODES, 256, 128);
    // layer 2: K=256 -> 256   (agg(h1) @ W2l^T + h1 @ W2r^T -> g_h2)
    k_aggregate<2, 1><<<AGGB, 256>>>(x);
    k_gemm_dual_relu<1, 2><<<g1, 256>>>(x, W2l, W2r, b2, N_NODES, 256, 256);
    // layer 3: K=256 -> 128   (agg(h2) @ W3l^T + h2 @ W3r^T -> g_h3)
    k_aggregate<2, 2><<<AGGB, 256>>>(x);
    k_gemm_dual_relu<2, 3><<<g3, 256>>>(x, W3l, W3r, b3, N_NODES, 128, 256);

    // global add pool
    k_zero_out<<<(out_size + 255) / 256, 256>>>(out, out_size);
    k_pool<<<AGGB, 256>>>(batch, out);
}

// round 5
// speedup vs baseline: 1.1734x; 1.1734x over previous
#include <cuda_runtime.h>
#include <cuda_bf16.h>
#include <cstdint>

#define N_NODES 50000
#define N_EDGES 1600000
#define N_GRAPHS 64

// ---------------- scratch (device globals; no allocations allowed) ----------
__device__ int   g_deg[N_NODES];
__device__ int   g_off[N_NODES + 1];
__device__ int   g_cursor[N_NODES];
__device__ float g_deginv[N_NODES];
__device__ int   g_srcs[N_EDGES];
__device__ int   g_partials[512];

__device__ float g_agg[(size_t)N_NODES * 256];
__device__ float g_h1 [(size_t)N_NODES * 256];
__device__ float g_h2 [(size_t)N_NODES * 256];
__device__ float g_h3 [(size_t)N_NODES * 128];

#define SCAN_CHUNK 128
#define N_CHUNKS ((N_NODES + SCAN_CHUNK - 1) / SCAN_CHUNK)   // 391

__device__ __forceinline__ const float* sel_buf(int sel, const float* x) {
    switch (sel) {
        case 0: return x;
        case 1: return g_h1;
        case 2: return g_h2;
        default: return g_agg;
    }
}
__device__ __forceinline__ float* sel_out(int sel) {
    switch (sel) {
        case 1: return g_h1;
        case 2: return g_h2;
        default: return g_h3;
    }
}

// ---------------- preprocessing: counting sort of edges by dst --------------
__global__ void k_zero_deg() {
    int i = blockIdx.x * blockDim.x + threadIdx.x;
    if (i < N_NODES) g_deg[i] = 0;
}
__global__ void k_count(const int* __restrict__ ei) {
    int i = blockIdx.x * blockDim.x + threadIdx.x;
    if (i >= N_EDGES) return;
    atomicAdd(&g_deg[ei[N_EDGES + i]], 1);
}
__global__ void k_chunk_sums() {
    __shared__ int s[SCAN_CHUNK];
    int i = blockIdx.x * SCAN_CHUNK + threadIdx.x;
    s[threadIdx.x] = (i < N_NODES) ? g_deg[i] : 0;
    __syncthreads();
    for (int stride = SCAN_CHUNK / 2; stride > 0; stride >>= 1) {
        if (threadIdx.x < stride) s[threadIdx.x] += s[threadIdx.x + stride];
        __syncthreads();
    }
    if (threadIdx.x == 0) g_partials[blockIdx.x] = s[0];
}
__global__ void k_scan_partials() {
    __shared__ int s[512];
    int t = threadIdx.x;
    s[t] = (t < N_CHUNKS) ? g_partials[t] : 0;
    __syncthreads();
    if (t == 0) {
        int run = 0;
        for (int i = 0; i < N_CHUNKS; ++i) { int v = s[i]; s[i] = run; run += v; }
        g_off[N_NODES] = N_EDGES;
    }
    __syncthreads();
    if (t < N_CHUNKS) g_partials[t] = s[t];
}
__global__ void k_scan_chunks() {
    __shared__ int sd[SCAN_CHUNK];
    __shared__ int so[SCAN_CHUNK];
    int i = blockIdx.x * SCAN_CHUNK + threadIdx.x;
    int d = (i < N_NODES) ? g_deg[i] : 0;
    sd[threadIdx.x] = d;
    __syncthreads();
    if (threadIdx.x == 0) {
        int run = g_partials[blockIdx.x];
        #pragma unroll 4
        for (int k = 0; k < SCAN_CHUNK; ++k) { so[k] = run; run += sd[k]; }
    }
    __syncthreads();
    if (i < N_NODES) {
        int o = so[threadIdx.x];
        g_off[i] = o;
        g_cursor[i] = o;
        g_deginv[i] = (d > 0) ? (1.0f / (float)d) : 0.0f;
    }
}
__global__ void k_fill(const int* __restrict__ ei) {
    int i = blockIdx.x * blockDim.x + threadIdx.x;
    if (i >= N_EDGES) return;
    int s = ei[i];
    int d = ei[N_EDGES + i];
    int pos = atomicAdd(&g_cursor[d], 1);
    g_srcs[pos] = s;
}

// ---------------- aggregation: warp per node, float4 gather -----------------
template <int NV4, int SRCSEL>
__global__ void k_aggregate(const float* __restrict__ xext) {
    int w = (blockIdx.x * blockDim.x + threadIdx.x) >> 5;
    if (w >= N_NODES) return;
    const float* __restrict__ X = sel_buf(SRCSEL, xext);
    int lane = threadIdx.x & 31;
    int beg = g_off[w];
    int end = g_off[w + 1];
    float inv = g_deginv[w];
    const float4* X4 = (const float4*)X;
    const int RV = NV4 * 32;

    float4 acc0[NV4], acc1[NV4];
    #pragma unroll
    for (int v = 0; v < NV4; ++v) {
        acc0[v] = make_float4(0.f, 0.f, 0.f, 0.f);
        acc1[v] = make_float4(0.f, 0.f, 0.f, 0.f);
    }
    int j = beg;
    for (; j + 2 <= end; j += 2) {
        int s0 = g_srcs[j], s1 = g_srcs[j + 1];
        #pragma unroll
        for (int v = 0; v < NV4; ++v) {
            float4 a = X4[(size_t)s0 * RV + v * 32 + lane];
            float4 b = X4[(size_t)s1 * RV + v * 32 + lane];
            acc0[v].x += a.x; acc0[v].y += a.y; acc0[v].z += a.z; acc0[v].w += a.w;
            acc1[v].x += b.x; acc1[v].y += b.y; acc1[v].z += b.z; acc1[v].w += b.w;
        }
    }
    if (j < end) {
        int s0 = g_srcs[j];
        #pragma unroll
        for (int v = 0; v < NV4; ++v) {
            float4 a = X4[(size_t)s0 * RV + v * 32 + lane];
            acc0[v].x += a.x; acc0[v].y += a.y; acc0[v].z += a.z; acc0[v].w += a.w;
        }
    }
    float4* O4 = (float4*)g_agg;
    #pragma unroll
    for (int v = 0; v < NV4; ++v) {
        float4 r;
        r.x = (acc0[v].x + acc1[v].x) * inv;
        r.y = (acc0[v].y + acc1[v].y) * inv;
        r.z = (acc0[v].z + acc1[v].z) * inv;
        r.w = (acc0[v].w + acc1[v].w) * inv;
        O4[(size_t)w * RV + v * 32 + lane] = r;
    }
}

// ---------------- bf16-split HMMA GEMM + bias + relu -------------------------
// C[M,N] = relu( A1·Wl^T + A2·Wr^T + bias ), computed as bf16 split:
//   X ≈ Xhi + Xlo;  C ≈ Ahi·Bhi + Ahi·Blo + Alo·Bhi  (fp32 accumulate)
// mma.sync.m16n8k16.row.col.f32.bf16.bf16.f32
// Block 128x128, 8 warps of 32(M)x64(N). K slabs of 32 fp32 (dual-A concat).

__device__ __forceinline__ void cvt_hilo(float4 v, uint2& hi, uint2& lo) {
    __nv_bfloat16 h0 = __float2bfloat16_rn(v.x);
    __nv_bfloat16 h1 = __float2bfloat16_rn(v.y);
    __nv_bfloat16 h2 = __float2bfloat16_rn(v.z);
    __nv_bfloat16 h3 = __float2bfloat16_rn(v.w);
    __nv_bfloat162 H01(h0, h1), H23(h2, h3);
    __nv_bfloat162 L01(__float2bfloat16_rn(v.x - __bfloat162float(h0)),
                       __float2bfloat16_rn(v.y - __bfloat162float(h1)));
    __nv_bfloat162 L23(__float2bfloat16_rn(v.z - __bfloat162float(h2)),
                       __float2bfloat16_rn(v.w - __bfloat162float(h3)));
    hi.x = *(uint32_t*)&H01; hi.y = *(uint32_t*)&H23;
    lo.x = *(uint32_t*)&L01; lo.y = *(uint32_t*)&L23;
}

__device__ __forceinline__ uint32_t lds32(const __nv_bfloat16* p) {
    return *(const uint32_t*)p;
}

__device__ __forceinline__ void mma16816(float* c, const uint32_t* a, uint32_t b0, uint32_t b1) {
    asm volatile(
        "mma.sync.aligned.m16n8k16.row.col.f32.bf16.bf16.f32 "
        "{%0,%1,%2,%3}, {%4,%5,%6,%7}, {%8,%9}, {%0,%1,%2,%3};"
        : "+f"(c[0]), "+f"(c[1]), "+f"(c[2]), "+f"(c[3])
        : "r"(a[0]), "r"(a[1]), "r"(a[2]), "r"(a[3]), "r"(b0), "r"(b1));
}

#define GLD 40   // smem leading dim in bf16 elems (80B rows: 16B aligned, bank-stride 20)

template <int K, int N, int A2SEL, int CSEL>
__global__ __launch_bounds__(256)
void k_gemm_mma(const float* __restrict__ xext,
                const float* __restrict__ Wl, const float* __restrict__ Wr,
                const float* __restrict__ bias) {
    __shared__ __nv_bfloat16 sAhi[128 * GLD];
    __shared__ __nv_bfloat16 sAlo[128 * GLD];
    __shared__ __nv_bfloat16 sBhi[128 * GLD];
    __shared__ __nv_bfloat16 sBlo[128 * GLD];

    const float* __restrict__ A1 = g_agg;
    const float* __restrict__ A2 = sel_buf(A2SEL, xext);
    float* __restrict__ C = sel_out(CSEL);

    int t = threadIdx.x;
    int lane = t & 31, wid = t >> 5;
    int wm = (wid & 3) * 32;
    int wn = (wid >> 2) * 64;
    int bm = blockIdx.x * 128;
    int bn = blockIdx.y * 128;
    int g = lane >> 2, tq = lane & 3;

    float acc[2][8][4];
    #pragma unroll
    for (int i = 0; i < 2; ++i)
        #pragma unroll
        for (int j = 0; j < 8; ++j)
            #pragma unroll
            for (int q = 0; q < 4; ++q) acc[i][j][q] = 0.f;

    constexpr int HALF = K / 32;
    constexpr int SLABS = 2 * HALF;

    for (int s = 0; s < SLABS; ++s) {
        const float* Ap; const float* Bp; int koff;
        if (s < HALF) { Ap = A1; Bp = Wl; koff = s * 32; }
        else          { Ap = A2; Bp = Wr; koff = (s - HALF) * 32; }

        __syncthreads();
        // A slab: 128 rows x 32 floats = 1024 float4 -> 4/thread
        #pragma unroll
        for (int i = 0; i < 4; ++i) {
            int idx = t + i * 256;
            int row = idx >> 3, q = idx & 7;
            int gm = bm + row;
            float4 v = make_float4(0.f, 0.f, 0.f, 0.f);
            if (gm < N_NODES) v = *(const float4*)(Ap + (size_t)gm * K + koff + q * 4);
            uint2 hi, lo;
            cvt_hilo(v, hi, lo);
            *(uint2*)&sAhi[row * GLD + q * 4] = hi;
            *(uint2*)&sAlo[row * GLD + q * 4] = lo;
        }
        // B slab: 128 rows x 32 floats
        #pragma unroll
        for (int i = 0; i < 4; ++i) {
            int idx = t + i * 256;
            int row = idx >> 3, q = idx & 7;
            float4 v = *(const float4*)(Bp + (size_t)(bn + row) * K + koff + q * 4);
            uint2 hi, lo;
            cvt_hilo(v, hi, lo);
            *(uint2*)&sBhi[row * GLD + q * 4] = hi;
            *(uint2*)&sBlo[row * GLD + q * 4] = lo;
        }
        __syncthreads();

        #pragma unroll
        for (int k16 = 0; k16 < 32; k16 += 16) {
            uint32_t ah[2][4], al[2][4];
            #pragma unroll
            for (int i = 0; i < 2; ++i) {
                const __nv_bfloat16* ph = &sAhi[(wm + i * 16 + g) * GLD + k16 + 2 * tq];
                const __nv_bfloat16* pl = &sAlo[(wm + i * 16 + g) * GLD + k16 + 2 * tq];
                ah[i][0] = lds32(ph);
                ah[i][1] = lds32(ph + 8 * GLD);
                ah[i][2] = lds32(ph + 8);
                ah[i][3] = lds32(ph + 8 * GLD + 8);
                al[i][0] = lds32(pl);
                al[i][1] = lds32(pl + 8 * GLD);
                al[i][2] = lds32(pl + 8);
                al[i][3] = lds32(pl + 8 * GLD + 8);
            }
            #pragma unroll
            for (int j = 0; j < 8; ++j) {
                const __nv_bfloat16* pbh = &sBhi[(wn + j * 8 + g) * GLD + k16 + 2 * tq];
                const __nv_bfloat16* pbl = &sBlo[(wn + j * 8 + g) * GLD + k16 + 2 * tq];
                uint32_t bh0 = lds32(pbh), bh1 = lds32(pbh + 8);
                uint32_t bl0 = lds32(pbl), bl1 = lds32(pbl + 8);
                #pragma unroll
                for (int i = 0; i < 2; ++i) mma16816(acc[i][j], ah[i], bh0, bh1);
                #pragma unroll
                for (int i = 0; i < 2; ++i) mma16816(acc[i][j], ah[i], bl0, bl1);
                #pragma unroll
                for (int i = 0; i < 2; ++i) mma16816(acc[i][j], al[i], bh0, bh1);
            }
        }
    }

    // epilogue: bias + relu, float2 stores
    #pragma unroll
    for (int i = 0; i < 2; ++i) {
        int row0 = bm + wm + i * 16 + g;
        int row1 = row0 + 8;
        #pragma unroll
        for (int j = 0; j < 8; ++j) {
            int col = bn + wn + j * 8 + 2 * tq;
            float b0 = __ldg(bias + col), b1 = __ldg(bias + col + 1);
            if (row0 < N_NODES) {
                float2 o = { fmaxf(acc[i][j][0] + b0, 0.f), fmaxf(acc[i][j][1] + b1, 0.f) };
                *(float2*)(C + (size_t)row0 * N + col) = o;
            }
            if (row1 < N_NODES) {
                float2 o = { fmaxf(acc[i][j][2] + b0, 0.f), fmaxf(acc[i][j][3] + b1, 0.f) };
                *(float2*)(C + (size_t)row1 * N + col) = o;
            }
        }
    }
}

// ---------------- global add pool -------------------------------------------
__global__ void k_zero_out(float* out, int n) {
    int i = blockIdx.x * blockDim.x + threadIdx.x;
    if (i < n) out[i] = 0.f;
}
__global__ void k_pool(const int* __restrict__ batch, float* __restrict__ out) {
    int idx = blockIdx.x * blockDim.x + threadIdx.x;
    if (idx >= N_NODES * 32) return;
    int node = idx >> 5;
    int q    = idx & 31;
    int g    = batch[node];
    float4 v = ((const float4*)g_h3)[(size_t)node * 32 + q];
    float* p = out + (size_t)g * 128 + q * 4;
    atomicAdd(p + 0, v.x);
    atomicAdd(p + 1, v.y);
    atomicAdd(p + 2, v.z);
    atomicAdd(p + 3, v.w);
}

// ---------------- launch ----------------------------------------------------
extern "C" void kernel_launch(void* const* d_in, const int* in_sizes, int n_in,
                              void* d_out, int out_size) {
    const float* x     = (const float*)d_in[0];
    const int*   ei    = (const int*)d_in[1];     // int32 (JAX x64 disabled)
    const int*   batch = (const int*)d_in[2];
    const float* W1l = (const float*)d_in[3];
    const float* b1  = (const float*)d_in[4];
    const float* W1r = (const float*)d_in[5];
    const float* W2l = (const float*)d_in[6];
    const float* b2  = (const float*)d_in[7];
    const float* W2r = (const float*)d_in[8];
    const float* W3l = (const float*)d_in[9];
    const float* b3  = (const float*)d_in[10];
    const float* W3r = (const float*)d_in[11];
    float* out = (float*)d_out;

    const int EB   = (N_EDGES + 255) / 256;
    const int NBK  = (N_NODES + 255) / 256;
    const int AGGB = (N_NODES * 32 + 255) / 256;

    // preprocessing: counting sort of edges by dst
    k_zero_deg<<<NBK, 256>>>();
    k_count<<<EB, 256>>>(ei);
    k_chunk_sums<<<N_CHUNKS, SCAN_CHUNK>>>();
    k_scan_partials<<<1, 512>>>();
    k_scan_chunks<<<N_CHUNKS, SCAN_CHUNK>>>();
    k_fill<<<EB, 256>>>(ei);

    dim3 gm1((N_NODES + 127) / 128, 2);   // N=256
    dim3 gm3((N_NODES + 127) / 128, 1);   // N=128

    // layer 1: K=128 -> 256
    k_aggregate<1, 0><<<AGGB, 256>>>(x);
    k_gemm_mma<128, 256, 0, 1><<<gm1, 256>>>(x, W1l, W1r, b1);
    // layer 2: K=256 -> 256
    k_aggregate<2, 1><<<AGGB, 256>>>(x);
    k_gemm_mma<256, 256, 1, 2><<<gm1, 256>>>(x, W2l, W2r, b2);
    // layer 3: K=256 -> 128
    k_aggregate<2, 2><<<AGGB, 256>>>(x);
    k_gemm_mma<256, 128, 2, 3><<<gm3, 256>>>(x, W3l, W3r, b3);

    // global add pool
    k_zero_out<<<(out_size + 255) / 256, 256>>>(out, out_size);
    k_pool<<<AGGB, 256>>>(batch, out);
}

// round 6
// speedup vs baseline: 1.3779x; 1.1743x over previous
#include <cuda_runtime.h>
#include <cuda_bf16.h>
#include <cuda_fp16.h>
#include <cstdint>

#define N_NODES 50000
#define N_EDGES 1600000
#define N_GRAPHS 64

// ---------------- scratch (device globals; no allocations allowed) ----------
__device__ int   g_deg[N_NODES];
__device__ int   g_off[N_NODES + 1];
__device__ int   g_cursor[N_NODES];
__device__ float g_deginv[N_NODES];
__device__ int   g_srcs[N_EDGES];
__device__ int   g_partials[512];
__device__ int   g_gofs[N_GRAPHS + 1];

__device__ float g_agg[(size_t)N_NODES * 256];
__device__ float g_h1 [(size_t)N_NODES * 256];
__device__ float g_h2 [(size_t)N_NODES * 256];
__device__ float g_h3 [(size_t)N_NODES * 128];
__device__ __half g_fh[(size_t)N_NODES * 256];   // fp16 feature copy for gathers

#define SCAN_CHUNK 128
#define N_CHUNKS ((N_NODES + SCAN_CHUNK - 1) / SCAN_CHUNK)   // 391

__device__ __forceinline__ const float* sel_buf(int sel, const float* x) {
    switch (sel) {
        case 0: return x;
        case 1: return g_h1;
        case 2: return g_h2;
        default: return g_agg;
    }
}
__device__ __forceinline__ float* sel_out(int sel) {
    switch (sel) {
        case 1: return g_h1;
        case 2: return g_h2;
        default: return g_h3;
    }
}

// ---------------- preprocessing: counting sort of edges by dst --------------
__global__ void k_zero_deg() {
    int i = blockIdx.x * blockDim.x + threadIdx.x;
    if (i < N_NODES) g_deg[i] = 0;
}
__global__ void k_count(const int* __restrict__ ei) {
    int i = blockIdx.x * blockDim.x + threadIdx.x;
    if (i >= N_EDGES) return;
    atomicAdd(&g_deg[ei[N_EDGES + i]], 1);
}
__global__ void k_chunk_sums() {
    __shared__ int s[SCAN_CHUNK];
    int i = blockIdx.x * SCAN_CHUNK + threadIdx.x;
    s[threadIdx.x] = (i < N_NODES) ? g_deg[i] : 0;
    __syncthreads();
    for (int stride = SCAN_CHUNK / 2; stride > 0; stride >>= 1) {
        if (threadIdx.x < stride) s[threadIdx.x] += s[threadIdx.x + stride];
        __syncthreads();
    }
    if (threadIdx.x == 0) g_partials[blockIdx.x] = s[0];
}
__global__ void k_scan_partials() {
    __shared__ int s[512];
    int t = threadIdx.x;
    s[t] = (t < N_CHUNKS) ? g_partials[t] : 0;
    __syncthreads();
    if (t == 0) {
        int run = 0;
        for (int i = 0; i < N_CHUNKS; ++i) { int v = s[i]; s[i] = run; run += v; }
        g_off[N_NODES] = N_EDGES;
    }
    __syncthreads();
    if (t < N_CHUNKS) g_partials[t] = s[t];
}
__global__ void k_scan_chunks() {
    __shared__ int sd[SCAN_CHUNK];
    __shared__ int so[SCAN_CHUNK];
    int i = blockIdx.x * SCAN_CHUNK + threadIdx.x;
    int d = (i < N_NODES) ? g_deg[i] : 0;
    sd[threadIdx.x] = d;
    __syncthreads();
    if (threadIdx.x == 0) {
        int run = g_partials[blockIdx.x];
        #pragma unroll 4
        for (int k = 0; k < SCAN_CHUNK; ++k) { so[k] = run; run += sd[k]; }
    }
    __syncthreads();
    if (i < N_NODES) {
        int o = so[threadIdx.x];
        g_off[i] = o;
        g_cursor[i] = o;
        g_deginv[i] = (d > 0) ? (1.0f / (float)d) : 0.0f;
    }
}
__global__ void k_fill(const int* __restrict__ ei) {
    int i = blockIdx.x * blockDim.x + threadIdx.x;
    if (i >= N_EDGES) return;
    int s = ei[i];
    int d = ei[N_EDGES + i];
    int pos = atomicAdd(&g_cursor[d], 1);
    g_srcs[pos] = s;
}
// graph segment boundaries from sorted batch: g_gofs[g] = first node with batch >= g
__global__ void k_gofs(const int* __restrict__ batch) {
    int i = blockIdx.x * blockDim.x + threadIdx.x;
    if (i >= N_NODES) return;
    int b = batch[i];
    if (i == 0) {
        for (int g = 0; g <= b; ++g) g_gofs[g] = 0;
    } else {
        int p = batch[i - 1];
        if (p != b)
            for (int g = p + 1; g <= b; ++g) g_gofs[g] = i;
    }
    if (i == N_NODES - 1)
        for (int g = b + 1; g <= N_GRAPHS; ++g) g_gofs[g] = N_NODES;
}

// ---------------- x -> fp16 copy --------------------------------------------
__global__ void k_convert_x(const float* __restrict__ x) {
    int idx = blockIdx.x * blockDim.x + threadIdx.x;   // float4 index
    if (idx >= N_NODES * 32) return;
    float4 v = ((const float4*)x)[idx];
    __half2 a = __floats2half2_rn(v.x, v.y);
    __half2 b = __floats2half2_rn(v.z, v.w);
    uint2 pk = { *(uint32_t*)&a, *(uint32_t*)&b };
    *(uint2*)(g_fh + (size_t)idx * 4) = pk;
}

// ---------------- aggregation: warp per node, fp16 gather, fp32 accum -------
// HV: half2 per lane (K=128 -> 2, K=256 -> 4). Reads g_fh, writes g_agg fp32.
template <int HV>
__global__ void k_aggregate_f16() {
    int w = (blockIdx.x * blockDim.x + threadIdx.x) >> 5;
    if (w >= N_NODES) return;
    int lane = threadIdx.x & 31;
    int beg = g_off[w];
    int end = g_off[w + 1];
    float inv = g_deginv[w];
    const int RV = HV * 32;                      // half2 per row
    const __half* base = g_fh;

    float2 acc0[HV], acc1[HV];
    #pragma unroll
    for (int v = 0; v < HV; ++v) {
        acc0[v] = make_float2(0.f, 0.f);
        acc1[v] = make_float2(0.f, 0.f);
    }

    int j = beg;
    for (; j + 2 <= end; j += 2) {
        int s0 = g_srcs[j], s1 = g_srcs[j + 1];
        const __half* p0 = base + ((size_t)s0 * RV + lane * HV) * 2;
        const __half* p1 = base + ((size_t)s1 * RV + lane * HV) * 2;
        __half2 h0[HV], h1[HV];
        if (HV == 4) {
            uint4 v0 = *(const uint4*)p0;
            uint4 v1 = *(const uint4*)p1;
            h0[0] = *(__half2*)&v0.x; h0[1] = *(__half2*)&v0.y;
            h0[2] = *(__half2*)&v0.z; h0[3] = *(__half2*)&v0.w;
            h1[0] = *(__half2*)&v1.x; h1[1] = *(__half2*)&v1.y;
            h1[2] = *(__half2*)&v1.z; h1[3] = *(__half2*)&v1.w;
        } else {
            uint2 v0 = *(const uint2*)p0;
            uint2 v1 = *(const uint2*)p1;
            h0[0] = *(__half2*)&v0.x; h0[1] = *(__half2*)&v0.y;
            h1[0] = *(__half2*)&v1.x; h1[1] = *(__half2*)&v1.y;
        }
        #pragma unroll
        for (int v = 0; v < HV; ++v) {
            float2 f0 = __half22float2(h0[v]);
            float2 f1 = __half22float2(h1[v]);
            acc0[v].x += f0.x; acc0[v].y += f0.y;
            acc1[v].x += f1.x; acc1[v].y += f1.y;
        }
    }
    if (j < end) {
        int s0 = g_srcs[j];
        const __half* p0 = base + ((size_t)s0 * RV + lane * HV) * 2;
        __half2 h0[HV];
        if (HV == 4) {
            uint4 v0 = *(const uint4*)p0;
            h0[0] = *(__half2*)&v0.x; h0[1] = *(__half2*)&v0.y;
            h0[2] = *(__half2*)&v0.z; h0[3] = *(__half2*)&v0.w;
        } else {
            uint2 v0 = *(const uint2*)p0;
            h0[0] = *(__half2*)&v0.x; h0[1] = *(__half2*)&v0.y;
        }
        #pragma unroll
        for (int v = 0; v < HV; ++v) {
            float2 f0 = __half22float2(h0[v]);
            acc0[v].x += f0.x; acc0[v].y += f0.y;
        }
    }

    float2* O2 = (float2*)g_agg;
    #pragma unroll
    for (int v = 0; v < HV; ++v) {
        float2 r;
        r.x = (acc0[v].x + acc1[v].x) * inv;
        r.y = (acc0[v].y + acc1[v].y) * inv;
        O2[(size_t)w * RV + lane * HV + v] = r;
    }
}

// ---------------- bf16-split HMMA GEMM + bias + relu -------------------------
__device__ __forceinline__ void cvt_hilo(float4 v, uint2& hi, uint2& lo) {
    __nv_bfloat16 h0 = __float2bfloat16_rn(v.x);
    __nv_bfloat16 h1 = __float2bfloat16_rn(v.y);
    __nv_bfloat16 h2 = __float2bfloat16_rn(v.z);
    __nv_bfloat16 h3 = __float2bfloat16_rn(v.w);
    __nv_bfloat162 H01(h0, h1), H23(h2, h3);
    __nv_bfloat162 L01(__float2bfloat16_rn(v.x - __bfloat162float(h0)),
                       __float2bfloat16_rn(v.y - __bfloat162float(h1)));
    __nv_bfloat162 L23(__float2bfloat16_rn(v.z - __bfloat162float(h2)),
                       __float2bfloat16_rn(v.w - __bfloat162float(h3)));
    hi.x = *(uint32_t*)&H01; hi.y = *(uint32_t*)&H23;
    lo.x = *(uint32_t*)&L01; lo.y = *(uint32_t*)&L23;
}
__device__ __forceinline__ uint32_t lds32(const __nv_bfloat16* p) {
    return *(const uint32_t*)p;
}
__device__ __forceinline__ void mma16816(float* c, const uint32_t* a, uint32_t b0, uint32_t b1) {
    asm volatile(
        "mma.sync.aligned.m16n8k16.row.col.f32.bf16.bf16.f32 "
        "{%0,%1,%2,%3}, {%4,%5,%6,%7}, {%8,%9}, {%0,%1,%2,%3};"
        : "+f"(c[0]), "+f"(c[1]), "+f"(c[2]), "+f"(c[3])
        : "r"(a[0]), "r"(a[1]), "r"(a[2]), "r"(a[3]), "r"(b0), "r"(b1));
}

#define GLD 40   // smem leading dim in bf16 elems

template <int K, int N, int A2SEL, int CSEL, int WF16>
__global__ __launch_bounds__(256)
void k_gemm_mma(const float* __restrict__ xext,
                const float* __restrict__ Wl, const float* __restrict__ Wr,
                const float* __restrict__ bias) {
    __shared__ __nv_bfloat16 sAhi[128 * GLD];
    __shared__ __nv_bfloat16 sAlo[128 * GLD];
    __shared__ __nv_bfloat16 sBhi[128 * GLD];
    __shared__ __nv_bfloat16 sBlo[128 * GLD];

    const float* __restrict__ A1 = g_agg;
    const float* __restrict__ A2 = sel_buf(A2SEL, xext);
    float* __restrict__ C = sel_out(CSEL);

    int t = threadIdx.x;
    int lane = t & 31, wid = t >> 5;
    int wm = (wid & 3) * 32;
    int wn = (wid >> 2) * 64;
    int bm = blockIdx.x * 128;
    int bn = blockIdx.y * 128;
    int g = lane >> 2, tq = lane & 3;

    float acc[2][8][4];
    #pragma unroll
    for (int i = 0; i < 2; ++i)
        #pragma unroll
        for (int j = 0; j < 8; ++j)
            #pragma unroll
            for (int q = 0; q < 4; ++q) acc[i][j][q] = 0.f;

    constexpr int HALF = K / 32;
    constexpr int SLABS = 2 * HALF;

    for (int s = 0; s < SLABS; ++s) {
        const float* Ap; const float* Bp; int koff;
        if (s < HALF) { Ap = A1; Bp = Wl; koff = s * 32; }
        else          { Ap = A2; Bp = Wr; koff = (s - HALF) * 32; }

        __syncthreads();
        #pragma unroll
        for (int i = 0; i < 4; ++i) {
            int idx = t + i * 256;
            int row = idx >> 3, q = idx & 7;
            int gm = bm + row;
            float4 v = make_float4(0.f, 0.f, 0.f, 0.f);
            if (gm < N_NODES) v = *(const float4*)(Ap + (size_t)gm * K + koff + q * 4);
            uint2 hi, lo;
            cvt_hilo(v, hi, lo);
            *(uint2*)&sAhi[row * GLD + q * 4] = hi;
            *(uint2*)&sAlo[row * GLD + q * 4] = lo;
        }
        #pragma unroll
        for (int i = 0; i < 4; ++i) {
            int idx = t + i * 256;
            int row = idx >> 3, q = idx & 7;
            float4 v = *(const float4*)(Bp + (size_t)(bn + row) * K + koff + q * 4);
            uint2 hi, lo;
            cvt_hilo(v, hi, lo);
            *(uint2*)&sBhi[row * GLD + q * 4] = hi;
            *(uint2*)&sBlo[row * GLD + q * 4] = lo;
        }
        __syncthreads();

        #pragma unroll
        for (int k16 = 0; k16 < 32; k16 += 16) {
            uint32_t ah[2][4], al[2][4];
            #pragma unroll
            for (int i = 0; i < 2; ++i) {
                const __nv_bfloat16* ph = &sAhi[(wm + i * 16 + g) * GLD + k16 + 2 * tq];
                const __nv_bfloat16* pl = &sAlo[(wm + i * 16 + g) * GLD + k16 + 2 * tq];
                ah[i][0] = lds32(ph);
                ah[i][1] = lds32(ph + 8 * GLD);
                ah[i][2] = lds32(ph + 8);
                ah[i][3] = lds32(ph + 8 * GLD + 8);
                al[i][0] = lds32(pl);
                al[i][1] = lds32(pl + 8 * GLD);
                al[i][2] = lds32(pl + 8);
                al[i][3] = lds32(pl + 8 * GLD + 8);
            }
            #pragma unroll
            for (int j = 0; j < 8; ++j) {
                const __nv_bfloat16* pbh = &sBhi[(wn + j * 8 + g) * GLD + k16 + 2 * tq];
                const __nv_bfloat16* pbl = &sBlo[(wn + j * 8 + g) * GLD + k16 + 2 * tq];
                uint32_t bh0 = lds32(pbh), bh1 = lds32(pbh + 8);
                uint32_t bl0 = lds32(pbl), bl1 = lds32(pbl + 8);
                #pragma unroll
                for (int i = 0; i < 2; ++i) mma16816(acc[i][j], ah[i], bh0, bh1);
                #pragma unroll
                for (int i = 0; i < 2; ++i) mma16816(acc[i][j], ah[i], bl0, bl1);
                #pragma unroll
                for (int i = 0; i < 2; ++i) mma16816(acc[i][j], al[i], bh0, bh1);
            }
        }
    }

    // epilogue: bias + relu; fp32 store + optional fp16 copy for next gather
    #pragma unroll
    for (int i = 0; i < 2; ++i) {
        int row0 = bm + wm + i * 16 + g;
        int row1 = row0 + 8;
        #pragma unroll
        for (int j = 0; j < 8; ++j) {
            int col = bn + wn + j * 8 + 2 * tq;
            float b0 = __ldg(bias + col), b1 = __ldg(bias + col + 1);
            if (row0 < N_NODES) {
                float2 o = { fmaxf(acc[i][j][0] + b0, 0.f), fmaxf(acc[i][j][1] + b1, 0.f) };
                *(float2*)(C + (size_t)row0 * N + col) = o;
                if (WF16) {
                    __half2 hh = __floats2half2_rn(o.x, o.y);
                    *(__half2*)(g_fh + (size_t)row0 * N + col) = hh;
                }
            }
            if (row1 < N_NODES) {
                float2 o = { fmaxf(acc[i][j][2] + b0, 0.f), fmaxf(acc[i][j][3] + b1, 0.f) };
                *(float2*)(C + (size_t)row1 * N + col) = o;
                if (WF16) {
                    __half2 hh = __floats2half2_rn(o.x, o.y);
                    *(__half2*)(g_fh + (size_t)row1 * N + col) = hh;
                }
            }
        }
    }
}

// ---------------- global add pool (segment-based, batch sorted) --------------
#define POOL_SPLIT 8
__global__ void k_zero_out(float* out, int n) {
    int i = blockIdx.x * blockDim.x + threadIdx.x;
    if (i < n) out[i] = 0.f;
}
__global__ void k_pool_seg(float* __restrict__ out) {
    int gph = blockIdx.x;
    int part = blockIdx.y;
    int c = threadIdx.x;             // 128 cols
    int beg = g_gofs[gph], end = g_gofs[gph + 1];
    float s = 0.f;
    for (int i = beg + part; i < end; i += POOL_SPLIT)
        s += g_h3[(size_t)i * 128 + c];
    atomicAdd(&out[gph * 128 + c], s);
}

// ---------------- launch ----------------------------------------------------
extern "C" void kernel_launch(void* const* d_in, const int* in_sizes, int n_in,
                              void* d_out, int out_size) {
    const float* x     = (const float*)d_in[0];
    const int*   ei    = (const int*)d_in[1];     // int32 (JAX x64 disabled)
    const int*   batch = (const int*)d_in[2];
    const float* W1l = (const float*)d_in[3];
    const float* b1  = (const float*)d_in[4];
    const float* W1r = (const float*)d_in[5];
    const float* W2l = (const float*)d_in[6];
    const float* b2  = (const float*)d_in[7];
    const float* W2r = (const float*)d_in[8];
    const float* W3l = (const float*)d_in[9];
    const float* b3  = (const float*)d_in[10];
    const float* W3r = (const float*)d_in[11];
    float* out = (float*)d_out;

    const int EB   = (N_EDGES + 255) / 256;
    const int NBK  = (N_NODES + 255) / 256;
    const int AGGB = (N_NODES * 32 + 255) / 256;

    // preprocessing: counting sort of edges by dst + graph offsets
    k_zero_deg<<<NBK, 256>>>();
    k_count<<<EB, 256>>>(ei);
    k_chunk_sums<<<N_CHUNKS, SCAN_CHUNK>>>();
    k_scan_partials<<<1, 512>>>();
    k_scan_chunks<<<N_CHUNKS, SCAN_CHUNK>>>();
    k_fill<<<EB, 256>>>(ei);
    k_gofs<<<NBK, 256>>>(batch);
    k_convert_x<<<(N_NODES * 32 + 255) / 256, 256>>>(x);

    dim3 gm1((N_NODES + 127) / 128, 2);   // N=256
    dim3 gm3((N_NODES + 127) / 128, 1);   // N=128

    // layer 1: K=128 -> 256
    k_aggregate_f16<2><<<AGGB, 256>>>();
    k_gemm_mma<128, 256, 0, 1, 1><<<gm1, 256>>>(x, W1l, W1r, b1);
    // layer 2: K=256 -> 256
    k_aggregate_f16<4><<<AGGB, 256>>>();
    k_gemm_mma<256, 256, 1, 2, 1><<<gm1, 256>>>(x, W2l, W2r, b2);
    // layer 3: K=256 -> 128
    k_aggregate_f16<4><<<AGGB, 256>>>();
    k_gemm_mma<256, 128, 2, 3, 0><<<gm3, 256>>>(x, W3l, W3r, b3);

    // global add pool (segment reduction)
    k_zero_out<<<(out_size + 255) / 256, 256>>>(out, out_size);
    dim3 pg(N_GRAPHS, POOL_SPLIT);
    k_pool_seg<<<pg, 128>>>(out);
}

// round 7
// speedup vs baseline: 1.9051x; 1.3826x over previous
#include <cuda_runtime.h>
#include <cuda_bf16.h>
#include <cuda_fp16.h>
#include <cstdint>

#define N_NODES 50000
#define N_EDGES 1600000
#define N_GRAPHS 64

// ---------------- scratch (device globals; no allocations allowed) ----------
__device__ int   g_deg[N_NODES];
__device__ int   g_off[N_NODES + 1];
__device__ int   g_cursor[N_NODES];
__device__ float g_deginv[N_NODES];
__device__ int   g_srcs[N_EDGES];
__device__ int   g_partials[512];
__device__ int   g_gofs[N_GRAPHS + 1];

// packed bf16 hi|lo operand buffers ([row, 2K]: cols 0..K-1 = hi, K..2K-1 = lo)
__device__ __nv_bfloat16 g_a1p[(size_t)N_NODES * 512];   // aggregated features
__device__ __nv_bfloat16 g_xp [(size_t)N_NODES * 256];   // x packed
__device__ __nv_bfloat16 g_h1p[(size_t)N_NODES * 512];   // h1 packed
__device__ __nv_bfloat16 g_h2p[(size_t)N_NODES * 512];   // h2 packed
__device__ __nv_bfloat16 g_wlp[256 * 512];               // Wl packed (per layer)
__device__ __nv_bfloat16 g_wrp[256 * 512];               // Wr packed (per layer)
__device__ __half g_fh[(size_t)N_NODES * 256];           // fp16 gather copy
__device__ float g_h3[(size_t)N_NODES * 128];            // final fp32 for pool

#define SCAN_CHUNK 128
#define N_CHUNKS ((N_NODES + SCAN_CHUNK - 1) / SCAN_CHUNK)   // 391

// ---------------- small asm helpers -----------------------------------------
__device__ __forceinline__ uint32_t smem_u32(const void* p) {
    uint32_t r;
    asm("{ .reg .u64 t; cvta.to.shared.u64 t, %1; cvt.u32.u64 %0, t; }" : "=r"(r) : "l"(p));
    return r;
}
__device__ __forceinline__ void cp_async16(uint32_t dst, const void* src, int src_bytes) {
    asm volatile("cp.async.cg.shared.global [%0], [%1], 16, %2;"
                 :: "r"(dst), "l"(src), "r"(src_bytes));
}
__device__ __forceinline__ void cp_commit() {
    asm volatile("cp.async.commit_group;" ::: "memory");
}
template <int NPend>
__device__ __forceinline__ void cp_wait() {
    asm volatile("cp.async.wait_group %0;" :: "n"(NPend) : "memory");
}

// ---------------- preprocessing: counting sort of edges by dst --------------
__global__ void k_zero_deg() {
    int i = blockIdx.x * blockDim.x + threadIdx.x;
    if (i < N_NODES) g_deg[i] = 0;
}
__global__ void k_count(const int* __restrict__ ei) {
    int i = blockIdx.x * blockDim.x + threadIdx.x;
    if (i >= N_EDGES) return;
    atomicAdd(&g_deg[ei[N_EDGES + i]], 1);
}
__global__ void k_chunk_sums() {
    __shared__ int s[SCAN_CHUNK];
    int i = blockIdx.x * SCAN_CHUNK + threadIdx.x;
    s[threadIdx.x] = (i < N_NODES) ? g_deg[i] : 0;
    __syncthreads();
    for (int stride = SCAN_CHUNK / 2; stride > 0; stride >>= 1) {
        if (threadIdx.x < stride) s[threadIdx.x] += s[threadIdx.x + stride];
        __syncthreads();
    }
    if (threadIdx.x == 0) g_partials[blockIdx.x] = s[0];
}
__global__ void k_scan_partials() {
    __shared__ int s[512];
    int t = threadIdx.x;
    s[t] = (t < N_CHUNKS) ? g_partials[t] : 0;
    __syncthreads();
    if (t == 0) {
        int run = 0;
        for (int i = 0; i < N_CHUNKS; ++i) { int v = s[i]; s[i] = run; run += v; }
        g_off[N_NODES] = N_EDGES;
    }
    __syncthreads();
    if (t < N_CHUNKS) g_partials[t] = s[t];
}
__global__ void k_scan_chunks() {
    __shared__ int sd[SCAN_CHUNK];
    __shared__ int so[SCAN_CHUNK];
    int i = blockIdx.x * SCAN_CHUNK + threadIdx.x;
    int d = (i < N_NODES) ? g_deg[i] : 0;
    sd[threadIdx.x] = d;
    __syncthreads();
    if (threadIdx.x == 0) {
        int run = g_partials[blockIdx.x];
        #pragma unroll 4
        for (int k = 0; k < SCAN_CHUNK; ++k) { so[k] = run; run += sd[k]; }
    }
    __syncthreads();
    if (i < N_NODES) {
        int o = so[threadIdx.x];
        g_off[i] = o;
        g_cursor[i] = o;
        g_deginv[i] = (d > 0) ? (1.0f / (float)d) : 0.0f;
    }
}
__global__ void k_fill(const int* __restrict__ ei) {
    int i = blockIdx.x * blockDim.x + threadIdx.x;
    if (i >= N_EDGES) return;
    int s = ei[i];
    int d = ei[N_EDGES + i];
    int pos = atomicAdd(&g_cursor[d], 1);
    g_srcs[pos] = s;
}
__global__ void k_gofs(const int* __restrict__ batch) {
    int i = blockIdx.x * blockDim.x + threadIdx.x;
    if (i >= N_NODES) return;
    int b = batch[i];
    if (i == 0) {
        for (int g = 0; g <= b; ++g) g_gofs[g] = 0;
    } else {
        int p = batch[i - 1];
        if (p != b)
            for (int g = p + 1; g <= b; ++g) g_gofs[g] = i;
    }
    if (i == N_NODES - 1)
        for (int g = b + 1; g <= N_GRAPHS; ++g) g_gofs[g] = N_NODES;
}

// ---------------- packing helpers -------------------------------------------
__device__ __forceinline__ void bf_pair(float x, float y, __nv_bfloat162& H, __nv_bfloat162& L) {
    __nv_bfloat16 h0 = __float2bfloat16_rn(x);
    __nv_bfloat16 h1 = __float2bfloat16_rn(y);
    H = __nv_bfloat162(h0, h1);
    L = __nv_bfloat162(__float2bfloat16_rn(x - __bfloat162float(h0)),
                       __float2bfloat16_rn(y - __bfloat162float(h1)));
}

// x -> fp16 copy + packed bf16
__global__ void k_convert_x(const float* __restrict__ x) {
    int idx = blockIdx.x * blockDim.x + threadIdx.x;   // float4 index, [0, M*32)
    if (idx >= N_NODES * 32) return;
    int m = idx >> 5, q = idx & 31;
    float4 v = ((const float4*)x)[idx];
    __half2 a = __floats2half2_rn(v.x, v.y);
    __half2 b = __floats2half2_rn(v.z, v.w);
    uint2 pk = { *(uint32_t*)&a, *(uint32_t*)&b };
    *(uint2*)(g_fh + (size_t)idx * 4) = pk;
    __nv_bfloat162 H0, L0, H1, L1;
    bf_pair(v.x, v.y, H0, L0);
    bf_pair(v.z, v.w, H1, L1);
    __nv_bfloat16* row = g_xp + (size_t)m * 256;
    *(__nv_bfloat162*)(row + q * 4)       = H0;
    *(__nv_bfloat162*)(row + q * 4 + 2)   = H1;
    *(__nv_bfloat162*)(row + 128 + q * 4)     = L0;
    *(__nv_bfloat162*)(row + 128 + q * 4 + 2) = L1;
}

// weights -> packed bf16 [N, 2K]
template <int K, int N>
__global__ void k_convert_w(const float* __restrict__ Wl, const float* __restrict__ Wr) {
    const int KQ = K / 4;
    int idx = blockIdx.x * blockDim.x + threadIdx.x;
    if (idx >= N * KQ) return;
    int n = idx / KQ, k4 = idx % KQ;
    float4 a = ((const float4*)Wl)[idx];
    float4 b = ((const float4*)Wr)[idx];
    __nv_bfloat162 H0, L0, H1, L1;
    bf_pair(a.x, a.y, H0, L0);
    bf_pair(a.z, a.w, H1, L1);
    __nv_bfloat16* rl = g_wlp + (size_t)n * 2 * K;
    *(__nv_bfloat162*)(rl + k4 * 4)         = H0;
    *(__nv_bfloat162*)(rl + k4 * 4 + 2)     = H1;
    *(__nv_bfloat162*)(rl + K + k4 * 4)     = L0;
    *(__nv_bfloat162*)(rl + K + k4 * 4 + 2) = L1;
    bf_pair(b.x, b.y, H0, L0);
    bf_pair(b.z, b.w, H1, L1);
    __nv_bfloat16* rr = g_wrp + (size_t)n * 2 * K;
    *(__nv_bfloat162*)(rr + k4 * 4)         = H0;
    *(__nv_bfloat162*)(rr + k4 * 4 + 2)     = H1;
    *(__nv_bfloat162*)(rr + K + k4 * 4)     = L0;
    *(__nv_bfloat162*)(rr + K + k4 * 4 + 2) = L1;
}

// ---------------- aggregation: warp per node, fp16 gather, fp32 accum -------
// writes packed bf16 hi|lo into g_a1p [M, 2K], K = HV*64
template <int HV>
__global__ void k_aggregate_f16() {
    int w = (blockIdx.x * blockDim.x + threadIdx.x) >> 5;
    if (w >= N_NODES) return;
    int lane = threadIdx.x & 31;
    int beg = g_off[w];
    int end = g_off[w + 1];
    float inv = g_deginv[w];
    const int RV = HV * 32;
    const __half* base = g_fh;

    float2 acc0[HV], acc1[HV];
    #pragma unroll
    for (int v = 0; v < HV; ++v) {
        acc0[v] = make_float2(0.f, 0.f);
        acc1[v] = make_float2(0.f, 0.f);
    }
    int j = beg;
    for (; j + 2 <= end; j += 2) {
        int s0 = g_srcs[j], s1 = g_srcs[j + 1];
        const __half* p0 = base + ((size_t)s0 * RV + lane * HV) * 2;
        const __half* p1 = base + ((size_t)s1 * RV + lane * HV) * 2;
        __half2 h0[HV], h1[HV];
        if (HV == 4) {
            uint4 v0 = *(const uint4*)p0;
            uint4 v1 = *(const uint4*)p1;
            h0[0] = *(__half2*)&v0.x; h0[1] = *(__half2*)&v0.y;
            h0[2] = *(__half2*)&v0.z; h0[3] = *(__half2*)&v0.w;
            h1[0] = *(__half2*)&v1.x; h1[1] = *(__half2*)&v1.y;
            h1[2] = *(__half2*)&v1.z; h1[3] = *(__half2*)&v1.w;
        } else {
            uint2 v0 = *(const uint2*)p0;
            uint2 v1 = *(const uint2*)p1;
            h0[0] = *(__half2*)&v0.x; h0[1] = *(__half2*)&v0.y;
            h1[0] = *(__half2*)&v1.x; h1[1] = *(__half2*)&v1.y;
        }
        #pragma unroll
        for (int v = 0; v < HV; ++v) {
            float2 f0 = __half22float2(h0[v]);
            float2 f1 = __half22float2(h1[v]);
            acc0[v].x += f0.x; acc0[v].y += f0.y;
            acc1[v].x += f1.x; acc1[v].y += f1.y;
        }
    }
    if (j < end) {
        int s0 = g_srcs[j];
        const __half* p0 = base + ((size_t)s0 * RV + lane * HV) * 2;
        __half2 h0[HV];
        if (HV == 4) {
            uint4 v0 = *(const uint4*)p0;
            h0[0] = *(__half2*)&v0.x; h0[1] = *(__half2*)&v0.y;
            h0[2] = *(__half2*)&v0.z; h0[3] = *(__half2*)&v0.w;
        } else {
            uint2 v0 = *(const uint2*)p0;
            h0[0] = *(__half2*)&v0.x; h0[1] = *(__half2*)&v0.y;
        }
        #pragma unroll
        for (int v = 0; v < HV; ++v) {
            float2 f0 = __half22float2(h0[v]);
            acc0[v].x += f0.x; acc0[v].y += f0.y;
        }
    }

    const int K = HV * 64;
    __nv_bfloat16* row = g_a1p + (size_t)w * 2 * K;
    #pragma unroll
    for (int v = 0; v < HV; ++v) {
        float rx = (acc0[v].x + acc1[v].x) * inv;
        float ry = (acc0[v].y + acc1[v].y) * inv;
        __nv_bfloat162 H, L;
        bf_pair(rx, ry, H, L);
        int e = (lane * HV + v) * 2;
        *(__nv_bfloat162*)(row + e)     = H;
        *(__nv_bfloat162*)(row + K + e) = L;
    }
}

// ---------------- bf16-split HMMA GEMM + bias + relu (cp.async pipelined) ----
__device__ __forceinline__ uint32_t lds32(const __nv_bfloat16* p) {
    return *(const uint32_t*)p;
}
__device__ __forceinline__ void mma16816(float* c, const uint32_t* a, uint32_t b0, uint32_t b1) {
    asm volatile(
        "mma.sync.aligned.m16n8k16.row.col.f32.bf16.bf16.f32 "
        "{%0,%1,%2,%3}, {%4,%5,%6,%7}, {%8,%9}, {%0,%1,%2,%3};"
        : "+f"(c[0]), "+f"(c[1]), "+f"(c[2]), "+f"(c[3])
        : "r"(a[0]), "r"(a[1]), "r"(a[2]), "r"(a[3]), "r"(b0), "r"(b1));
}

#define GLD 40                   // smem row stride in bf16
#define TILE (128 * GLD)         // one 128x32 tile (padded), in bf16 elems
#define GEMM_SMEM (2 * 4 * TILE * 2)   // 2 stages x 4 tiles x bytes = 81920

template <int K>
__device__ __forceinline__ void load_slab(
    int s, int bm, int bn, int t,
    const __nv_bfloat16* __restrict__ A1p, const __nv_bfloat16* __restrict__ A2p,
    __nv_bfloat16* dynsm)
{
    constexpr int HALF = K / 32;
    constexpr int W = 2 * K;
    const __nv_bfloat16* Ap;
    const __nv_bfloat16* Bp;
    int koff;
    if (s < HALF) { Ap = A1p; Bp = g_wlp; koff = s * 32; }
    else          { Ap = A2p; Bp = g_wrp; koff = (s - HALF) * 32; }

    __nv_bfloat16* stage = dynsm + (size_t)(s & 1) * 4 * TILE;
    __nv_bfloat16* sAhi = stage;
    __nv_bfloat16* sAlo = stage + TILE;
    __nv_bfloat16* sBhi = stage + 2 * TILE;
    __nv_bfloat16* sBlo = stage + 3 * TILE;

    #pragma unroll
    for (int i = 0; i < 2; ++i) {
        int idx = t + i * 256;
        int row = idx >> 2, q = idx & 3;
        int gm = bm + row;
        int ok = (gm < N_NODES) ? 16 : 0;
        int gmc = (gm < N_NODES) ? gm : 0;
        const __nv_bfloat16* srcA = Ap + (size_t)gmc * W + koff + q * 8;
        cp_async16(smem_u32(sAhi + row * GLD + q * 8), srcA, ok);
        cp_async16(smem_u32(sAlo + row * GLD + q * 8), srcA + K, ok);
        const __nv_bfloat16* srcB = Bp + (size_t)(bn + row) * W + koff + q * 8;
        cp_async16(smem_u32(sBhi + row * GLD + q * 8), srcB, 16);
        cp_async16(smem_u32(sBlo + row * GLD + q * 8), srcB + K, 16);
    }
    cp_commit();
}

// OUTSEL: 1 -> g_h1p + g_fh, 2 -> g_h2p + g_fh, 3 -> g_h3 (fp32)
template <int K, int N, int A2SEL, int OUTSEL>
__global__ __launch_bounds__(256)
void k_gemm_mma(const float* __restrict__ bias) {
    extern __shared__ __nv_bfloat16 dynsm[];

    const __nv_bfloat16* __restrict__ A1p = g_a1p;
    const __nv_bfloat16* __restrict__ A2p =
        (A2SEL == 0) ? g_xp : (A2SEL == 1) ? g_h1p : g_h2p;

    int t = threadIdx.x;
    int lane = t & 31, wid = t >> 5;
    int wm = (wid & 3) * 32;
    int wn = (wid >> 2) * 64;
    int bm = blockIdx.x * 128;
    int bn = blockIdx.y * 128;
    int g = lane >> 2, tq = lane & 3;

    float acc[2][8][4];
    #pragma unroll
    for (int i = 0; i < 2; ++i)
        #pragma unroll
        for (int j = 0; j < 8; ++j)
            #pragma unroll
            for (int q = 0; q < 4; ++q) acc[i][j][q] = 0.f;

    constexpr int SLABS = 2 * (K / 32);

    load_slab<K>(0, bm, bn, t, A1p, A2p, dynsm);

    for (int s = 0; s < SLABS; ++s) {
        if (s + 1 < SLABS) {
            load_slab<K>(s + 1, bm, bn, t, A1p, A2p, dynsm);
            cp_wait<1>();
        } else {
            cp_wait<0>();
        }
        __syncthreads();

        int b = s & 1;
        const __nv_bfloat16* pAhi = dynsm + (size_t)b * 4 * TILE;
        const __nv_bfloat16* pAlo = pAhi + TILE;
        const __nv_bfloat16* pBhi = pAhi + 2 * TILE;
        const __nv_bfloat16* pBlo = pAhi + 3 * TILE;

        #pragma unroll
        for (int k16 = 0; k16 < 32; k16 += 16) {
            uint32_t ah[2][4], al[2][4];
            #pragma unroll
            for (int i = 0; i < 2; ++i) {
                const __nv_bfloat16* ph = pAhi + (wm + i * 16 + g) * GLD + k16 + 2 * tq;
                const __nv_bfloat16* pl = pAlo + (wm + i * 16 + g) * GLD + k16 + 2 * tq;
                ah[i][0] = lds32(ph);
                ah[i][1] = lds32(ph + 8 * GLD);
                ah[i][2] = lds32(ph + 8);
                ah[i][3] = lds32(ph + 8 * GLD + 8);
                al[i][0] = lds32(pl);
                al[i][1] = lds32(pl + 8 * GLD);
                al[i][2] = lds32(pl + 8);
                al[i][3] = lds32(pl + 8 * GLD + 8);
            }
            #pragma unroll
            for (int j = 0; j < 8; ++j) {
                const __nv_bfloat16* pbh = pBhi + (wn + j * 8 + g) * GLD + k16 + 2 * tq;
                const __nv_bfloat16* pbl = pBlo + (wn + j * 8 + g) * GLD + k16 + 2 * tq;
                uint32_t bh0 = lds32(pbh), bh1 = lds32(pbh + 8);
                uint32_t bl0 = lds32(pbl), bl1 = lds32(pbl + 8);
                #pragma unroll
                for (int i = 0; i < 2; ++i) mma16816(acc[i][j], ah[i], bh0, bh1);
                #pragma unroll
                for (int i = 0; i < 2; ++i) mma16816(acc[i][j], ah[i], bl0, bl1);
                #pragma unroll
                for (int i = 0; i < 2; ++i) mma16816(acc[i][j], al[i], bh0, bh1);
            }
        }
        __syncthreads();
    }

    // epilogue
    #pragma unroll
    for (int i = 0; i < 2; ++i) {
        int rows[2] = { bm + wm + i * 16 + g, bm + wm + i * 16 + g + 8 };
        #pragma unroll
        for (int j = 0; j < 8; ++j) {
            int col = bn + wn + j * 8 + 2 * tq;
            float b0 = __ldg(bias + col), b1 = __ldg(bias + col + 1);
            #pragma unroll
            for (int h = 0; h < 2; ++h) {
                int row = rows[h];
                if (row >= N_NODES) continue;
                float ox = fmaxf(acc[i][j][h * 2 + 0] + b0, 0.f);
                float oy = fmaxf(acc[i][j][h * 2 + 1] + b1, 0.f);
                if (OUTSEL == 3) {
                    float2 o = { ox, oy };
                    *(float2*)(g_h3 + (size_t)row * N + col) = o;
                } else {
                    __nv_bfloat16* hp = (OUTSEL == 1) ? g_h1p : g_h2p;
                    __nv_bfloat162 H, L;
                    bf_pair(ox, oy, H, L);
                    *(__nv_bfloat162*)(hp + (size_t)row * 2 * N + col)     = H;
                    *(__nv_bfloat162*)(hp + (size_t)row * 2 * N + N + col) = L;
                    __half2 hh = __floats2half2_rn(ox, oy);
                    *(__half2*)(g_fh + (size_t)row * N + col) = hh;
                }
            }
        }
    }
}

// ---------------- global add pool (segment-based, batch sorted) --------------
#define POOL_SPLIT 8
__global__ void k_zero_out(float* out, int n) {
    int i = blockIdx.x * blockDim.x + threadIdx.x;
    if (i < n) out[i] = 0.f;
}
__global__ void k_pool_seg(float* __restrict__ out) {
    int gph = blockIdx.x;
    int part = blockIdx.y;
    int c = threadIdx.x;             // 128 cols
    int beg = g_gofs[gph], end = g_gofs[gph + 1];
    float s = 0.f;
    for (int i = beg + part; i < end; i += POOL_SPLIT)
        s += g_h3[(size_t)i * 128 + c];
    atomicAdd(&out[gph * 128 + c], s);
}

// ---------------- launch ----------------------------------------------------
extern "C" void kernel_launch(void* const* d_in, const int* in_sizes, int n_in,
                              void* d_out, int out_size) {
    const float* x     = (const float*)d_in[0];
    const int*   ei    = (const int*)d_in[1];     // int32 (JAX x64 disabled)
    const int*   batch = (const int*)d_in[2];
    const float* W1l = (const float*)d_in[3];
    const float* b1  = (const float*)d_in[4];
    const float* W1r = (const float*)d_in[5];
    const float* W2l = (const float*)d_in[6];
    const float* b2  = (const float*)d_in[7];
    const float* W2r = (const float*)d_in[8];
    const float* W3l = (const float*)d_in[9];
    const float* b3  = (const float*)d_in[10];
    const float* W3r = (const float*)d_in[11];
    float* out = (float*)d_out;

    const int EB   = (N_EDGES + 255) / 256;
    const int NBK  = (N_NODES + 255) / 256;
    const int AGGB = (N_NODES * 32 + 255) / 256;

    cudaFuncSetAttribute(k_gemm_mma<128, 256, 0, 1>, cudaFuncAttributeMaxDynamicSharedMemorySize, GEMM_SMEM);
    cudaFuncSetAttribute(k_gemm_mma<256, 256, 1, 2>, cudaFuncAttributeMaxDynamicSharedMemorySize, GEMM_SMEM);
    cudaFuncSetAttribute(k_gemm_mma<256, 128, 2, 3>, cudaFuncAttributeMaxDynamicSharedMemorySize, GEMM_SMEM);

    // preprocessing: counting sort of edges by dst + graph offsets
    k_zero_deg<<<NBK, 256>>>();
    k_count<<<EB, 256>>>(ei);
    k_chunk_sums<<<N_CHUNKS, SCAN_CHUNK>>>();
    k_scan_partials<<<1, 512>>>();
    k_scan_chunks<<<N_CHUNKS, SCAN_CHUNK>>>();
    k_fill<<<EB, 256>>>(ei);
    k_gofs<<<NBK, 256>>>(batch);
    k_convert_x<<<(N_NODES * 32 + 255) / 256, 256>>>(x);

    dim3 gm1((N_NODES + 127) / 128, 2);   // N=256
    dim3 gm3((N_NODES + 127) / 128, 1);   // N=128

    // layer 1: K=128 -> 256
    k_convert_w<128, 256><<<(256 * 32 + 255) / 256, 256>>>(W1l, W1r);
    k_aggregate_f16<2><<<AGGB, 256>>>();
    k_gemm_mma<128, 256, 0, 1><<<gm1, 256, GEMM_SMEM>>>(b1);
    // layer 2: K=256 -> 256
    k_convert_w<256, 256><<<(256 * 64 + 255) / 256, 256>>>(W2l, W2r);
    k_aggregate_f16<4><<<AGGB, 256>>>();
    k_gemm_mma<256, 256, 1, 2><<<gm1, 256, GEMM_SMEM>>>(b2);
    // layer 3: K=256 -> 128
    k_convert_w<256, 128><<<(128 * 64 + 255) / 256, 256>>>(W3l, W3r);
    k_aggregate_f16<4><<<AGGB, 256>>>();
    k_gemm_mma<256, 128, 2, 3><<<gm3, 256, GEMM_SMEM>>>(b3);

    // global add pool (segment reduction)
    k_zero_out<<<(out_size + 255) / 256, 256>>>(out, out_size);
    dim3 pg(N_GRAPHS, POOL_SPLIT);
    k_pool_seg<<<pg, 128>>>(out);
}

// round 8
// speedup vs baseline: 2.8541x; 1.4982x over previous
#include <cuda_runtime.h>
#include <cuda_fp16.h>
#include <cstdint>

#define N_NODES 50000
#define N_EDGES 1600000
#define N_GRAPHS 64

// ---------------- scratch (device globals; no allocations allowed) ----------
__device__ int   g_deg[N_NODES];
__device__ int   g_off[N_NODES + 1];
__device__ int   g_cursor[N_NODES];
__device__ float g_deginv[N_NODES];
__device__ int   g_srcs[N_EDGES];
__device__ int   g_partials[512];
__device__ int   g_gofs[N_GRAPHS + 1];

__device__ __half g_fA [(size_t)N_NODES * 256];   // feature ping
__device__ __half g_fB [(size_t)N_NODES * 256];   // feature pong
__device__ __half g_a1h[(size_t)N_NODES * 256];   // aggregated features (fp16)
__device__ __half g_wlh[256 * 256];               // Wl fp16 (per layer)
__device__ __half g_wrh[256 * 256];               // Wr fp16 (per layer)
__device__ float  g_h3 [(size_t)N_NODES * 128];   // final fp32 for pool

#define SCAN_CHUNK 128
#define N_CHUNKS ((N_NODES + SCAN_CHUNK - 1) / SCAN_CHUNK)   // 391

// ---------------- small asm helpers -----------------------------------------
__device__ __forceinline__ uint32_t smem_u32(const void* p) {
    uint32_t r;
    asm("{ .reg .u64 t; cvta.to.shared.u64 t, %1; cvt.u32.u64 %0, t; }" : "=r"(r) : "l"(p));
    return r;
}
__device__ __forceinline__ void cp_async16(uint32_t dst, const void* src, int src_bytes) {
    asm volatile("cp.async.cg.shared.global [%0], [%1], 16, %2;"
                 :: "r"(dst), "l"(src), "r"(src_bytes));
}
__device__ __forceinline__ void cp_commit() {
    asm volatile("cp.async.commit_group;" ::: "memory");
}
template <int NPend>
__device__ __forceinline__ void cp_wait() {
    asm volatile("cp.async.wait_group %0;" :: "n"(NPend) : "memory");
}

// ---------------- preprocessing: counting sort of edges by dst --------------
__global__ void k_zero_deg() {
    int i = blockIdx.x * blockDim.x + threadIdx.x;
    if (i < N_NODES) g_deg[i] = 0;
}
__global__ void k_count(const int* __restrict__ ei) {
    int i = blockIdx.x * blockDim.x + threadIdx.x;
    if (i >= N_EDGES) return;
    atomicAdd(&g_deg[ei[N_EDGES + i]], 1);
}
__global__ void k_chunk_sums() {
    __shared__ int s[SCAN_CHUNK];
    int i = blockIdx.x * SCAN_CHUNK + threadIdx.x;
    s[threadIdx.x] = (i < N_NODES) ? g_deg[i] : 0;
    __syncthreads();
    for (int stride = SCAN_CHUNK / 2; stride > 0; stride >>= 1) {
        if (threadIdx.x < stride) s[threadIdx.x] += s[threadIdx.x + stride];
        __syncthreads();
    }
    if (threadIdx.x == 0) g_partials[blockIdx.x] = s[0];
}
__global__ void k_scan_partials() {
    __shared__ int s[512];
    int t = threadIdx.x;
    s[t] = (t < N_CHUNKS) ? g_partials[t] : 0;
    __syncthreads();
    if (t == 0) {
        int run = 0;
        for (int i = 0; i < N_CHUNKS; ++i) { int v = s[i]; s[i] = run; run += v; }
        g_off[N_NODES] = N_EDGES;
    }
    __syncthreads();
    if (t < N_CHUNKS) g_partials[t] = s[t];
}
__global__ void k_scan_chunks() {
    __shared__ int sd[SCAN_CHUNK];
    __shared__ int so[SCAN_CHUNK];
    int i = blockIdx.x * SCAN_CHUNK + threadIdx.x;
    int d = (i < N_NODES) ? g_deg[i] : 0;
    sd[threadIdx.x] = d;
    __syncthreads();
    if (threadIdx.x == 0) {
        int run = g_partials[blockIdx.x];
        #pragma unroll 4
        for (int k = 0; k < SCAN_CHUNK; ++k) { so[k] = run; run += sd[k]; }
    }
    __syncthreads();
    if (i < N_NODES) {
        int o = so[threadIdx.x];
        g_off[i] = o;
        g_cursor[i] = o;
        g_deginv[i] = (d > 0) ? (1.0f / (float)d) : 0.0f;
    }
}
__global__ void k_fill(const int* __restrict__ ei) {
    int i = blockIdx.x * blockDim.x + threadIdx.x;
    if (i >= N_EDGES) return;
    int s = ei[i];
    int d = ei[N_EDGES + i];
    int pos = atomicAdd(&g_cursor[d], 1);
    g_srcs[pos] = s;
}
__global__ void k_gofs(const int* __restrict__ batch) {
    int i = blockIdx.x * blockDim.x + threadIdx.x;
    if (i >= N_NODES) return;
    int b = batch[i];
    if (i == 0) {
        for (int g = 0; g <= b; ++g) g_gofs[g] = 0;
    } else {
        int p = batch[i - 1];
        if (p != b)
            for (int g = p + 1; g <= b; ++g) g_gofs[g] = i;
    }
    if (i == N_NODES - 1)
        for (int g = b + 1; g <= N_GRAPHS; ++g) g_gofs[g] = N_NODES;
}

// ---------------- conversions ------------------------------------------------
// x -> g_fA fp16 (row stride 128)
__global__ void k_convert_x(const float* __restrict__ x) {
    int idx = blockIdx.x * blockDim.x + threadIdx.x;   // float4 index
    if (idx >= N_NODES * 32) return;
    float4 v = ((const float4*)x)[idx];
    __half2 a = __floats2half2_rn(v.x, v.y);
    __half2 b = __floats2half2_rn(v.z, v.w);
    uint2 pk = { *(uint32_t*)&a, *(uint32_t*)&b };
    *(uint2*)(g_fA + (size_t)idx * 4) = pk;
}
// weights -> fp16 [N, K]
template <int K, int N>
__global__ void k_convert_w(const float* __restrict__ Wl, const float* __restrict__ Wr) {
    int idx = blockIdx.x * blockDim.x + threadIdx.x;   // float4 index
    if (idx >= N * K / 4) return;
    float4 a = ((const float4*)Wl)[idx];
    float4 b = ((const float4*)Wr)[idx];
    __half2 a0 = __floats2half2_rn(a.x, a.y);
    __half2 a1 = __floats2half2_rn(a.z, a.w);
    __half2 b0 = __floats2half2_rn(b.x, b.y);
    __half2 b1 = __floats2half2_rn(b.z, b.w);
    uint2 pa = { *(uint32_t*)&a0, *(uint32_t*)&a1 };
    uint2 pb = { *(uint32_t*)&b0, *(uint32_t*)&b1 };
    *(uint2*)(g_wlh + (size_t)idx * 4) = pa;
    *(uint2*)(g_wrh + (size_t)idx * 4) = pb;
}

// ---------------- aggregation: warp per node, fp16 gather, fp32 accum -------
// HV: half2 per lane (K=128 -> 2, K=256 -> 4). INSEL: 0 -> g_fA, 1 -> g_fB.
// writes g_a1h fp16 (row stride K).
template <int HV, int INSEL>
__global__ void k_aggregate_f16() {
    int w = (blockIdx.x * blockDim.x + threadIdx.x) >> 5;
    if (w >= N_NODES) return;
    int lane = threadIdx.x & 31;
    int beg = g_off[w];
    int end = g_off[w + 1];
    float inv = g_deginv[w];
    const int RV = HV * 32;                      // half2 per row
    const __half* base = (INSEL == 0) ? g_fA : g_fB;

    float2 acc0[HV], acc1[HV];
    #pragma unroll
    for (int v = 0; v < HV; ++v) {
        acc0[v] = make_float2(0.f, 0.f);
        acc1[v] = make_float2(0.f, 0.f);
    }
    int j = beg;
    for (; j + 2 <= end; j += 2) {
        int s0 = g_srcs[j], s1 = g_srcs[j + 1];
        const __half* p0 = base + ((size_t)s0 * RV + lane * HV) * 2;
        const __half* p1 = base + ((size_t)s1 * RV + lane * HV) * 2;
        __half2 h0[HV], h1[HV];
        if (HV == 4) {
            uint4 v0 = *(const uint4*)p0;
            uint4 v1 = *(const uint4*)p1;
            h0[0] = *(__half2*)&v0.x; h0[1] = *(__half2*)&v0.y;
            h0[2] = *(__half2*)&v0.z; h0[3] = *(__half2*)&v0.w;
            h1[0] = *(__half2*)&v1.x; h1[1] = *(__half2*)&v1.y;
            h1[2] = *(__half2*)&v1.z; h1[3] = *(__half2*)&v1.w;
        } else {
            uint2 v0 = *(const uint2*)p0;
            uint2 v1 = *(const uint2*)p1;
            h0[0] = *(__half2*)&v0.x; h0[1] = *(__half2*)&v0.y;
            h1[0] = *(__half2*)&v1.x; h1[1] = *(__half2*)&v1.y;
        }
        #pragma unroll
        for (int v = 0; v < HV; ++v) {
            float2 f0 = __half22float2(h0[v]);
            float2 f1 = __half22float2(h1[v]);
            acc0[v].x += f0.x; acc0[v].y += f0.y;
            acc1[v].x += f1.x; acc1[v].y += f1.y;
        }
    }
    if (j < end) {
        int s0 = g_srcs[j];
        const __half* p0 = base + ((size_t)s0 * RV + lane * HV) * 2;
        __half2 h0[HV];
        if (HV == 4) {
            uint4 v0 = *(const uint4*)p0;
            h0[0] = *(__half2*)&v0.x; h0[1] = *(__half2*)&v0.y;
            h0[2] = *(__half2*)&v0.z; h0[3] = *(__half2*)&v0.w;
        } else {
            uint2 v0 = *(const uint2*)p0;
            h0[0] = *(__half2*)&v0.x; h0[1] = *(__half2*)&v0.y;
        }
        #pragma unroll
        for (int v = 0; v < HV; ++v) {
            float2 f0 = __half22float2(h0[v]);
            acc0[v].x += f0.x; acc0[v].y += f0.y;
        }
    }

    __half* row = g_a1h + (size_t)w * RV * 2;
    #pragma unroll
    for (int v = 0; v < HV; ++v) {
        float rx = (acc0[v].x + acc1[v].x) * inv;
        float ry = (acc0[v].y + acc1[v].y) * inv;
        __half2 r = __floats2half2_rn(rx, ry);
        *(__half2*)(row + (lane * HV + v) * 2) = r;
    }
}

// ---------------- fp16 HMMA GEMM + bias + relu (cp.async pipelined) ----------
__device__ __forceinline__ uint32_t lds32h(const __half* p) {
    return *(const uint32_t*)p;
}
__device__ __forceinline__ void mma16816h(float* c, const uint32_t* a, uint32_t b0, uint32_t b1) {
    asm volatile(
        "mma.sync.aligned.m16n8k16.row.col.f32.f16.f16.f32 "
        "{%0,%1,%2,%3}, {%4,%5,%6,%7}, {%8,%9}, {%0,%1,%2,%3};"
        : "+f"(c[0]), "+f"(c[1]), "+f"(c[2]), "+f"(c[3])
        : "r"(a[0]), "r"(a[1]), "r"(a[2]), "r"(a[3]), "r"(b0), "r"(b1));
}

#define GLD 40                    // smem row stride in halves (conflict-free)
#define TILEH (128 * GLD)         // one 128x32 tile in halves
#define GEMM_SMEM (2 * 2 * TILEH * 2)   // 2 stages x 2 tiles x 2B = 40960

template <int K>
__device__ __forceinline__ void load_slab(
    int s, int bm, int bn, int t,
    const __half* __restrict__ A1, const __half* __restrict__ A2,
    __half* dynsm)
{
    constexpr int HALF = K / 32;
    const __half* Ap;
    const __half* Bp;
    int koff;
    if (s < HALF) { Ap = A1; Bp = g_wlh; koff = s * 32; }
    else          { Ap = A2; Bp = g_wrh; koff = (s - HALF) * 32; }

    __half* stage = dynsm + (size_t)(s & 1) * 2 * TILEH;
    __half* sA = stage;
    __half* sB = stage + TILEH;

    #pragma unroll
    for (int i = 0; i < 2; ++i) {
        int idx = t + i * 256;
        int row = idx >> 2, q = idx & 3;
        int gm = bm + row;
        int ok = (gm < N_NODES) ? 16 : 0;
        int gmc = (gm < N_NODES) ? gm : 0;
        cp_async16(smem_u32(sA + row * GLD + q * 8), Ap + (size_t)gmc * K + koff + q * 8, ok);
        cp_async16(smem_u32(sB + row * GLD + q * 8), Bp + (size_t)(bn + row) * K + koff + q * 8, 16);
    }
    cp_commit();
}

// INSEL: A2 source buffer (0 -> g_fA, 1 -> g_fB)
// OUTSEL: 0 -> g_fB, 1 -> g_fA, 3 -> g_h3 (fp32)
template <int K, int N, int INSEL, int OUTSEL>
__global__ __launch_bounds__(256)
void k_gemm_f16(const float* __restrict__ bias) {
    extern __shared__ __half dynsm[];

    const __half* __restrict__ A1 = g_a1h;
    const __half* __restrict__ A2 = (INSEL == 0) ? g_fA : g_fB;

    int t = threadIdx.x;
    int lane = t & 31, wid = t >> 5;
    int wm = (wid & 3) * 32;
    int wn = (wid >> 2) * 64;
    int bm = blockIdx.x * 128;
    int bn = blockIdx.y * 128;
    int g = lane >> 2, tq = lane & 3;

    float acc[2][8][4];
    #pragma unroll
    for (int i = 0; i < 2; ++i)
        #pragma unroll
        for (int j = 0; j < 8; ++j)
            #pragma unroll
            for (int q = 0; q < 4; ++q) acc[i][j][q] = 0.f;

    constexpr int SLABS = 2 * (K / 32);

    load_slab<K>(0, bm, bn, t, A1, A2, dynsm);

    for (int s = 0; s < SLABS; ++s) {
        if (s + 1 < SLABS) {
            load_slab<K>(s + 1, bm, bn, t, A1, A2, dynsm);
            cp_wait<1>();
        } else {
            cp_wait<0>();
        }
        __syncthreads();

        const __half* pA = dynsm + (size_t)(s & 1) * 2 * TILEH;
        const __half* pB = pA + TILEH;

        #pragma unroll
        for (int k16 = 0; k16 < 32; k16 += 16) {
            uint32_t a[2][4];
            #pragma unroll
            for (int i = 0; i < 2; ++i) {
                const __half* ph = pA + (wm + i * 16 + g) * GLD + k16 + 2 * tq;
                a[i][0] = lds32h(ph);
                a[i][1] = lds32h(ph + 8 * GLD);
                a[i][2] = lds32h(ph + 8);
                a[i][3] = lds32h(ph + 8 * GLD + 8);
            }
            #pragma unroll
            for (int j = 0; j < 8; ++j) {
                const __half* pb = pB + (wn + j * 8 + g) * GLD + k16 + 2 * tq;
                uint32_t b0 = lds32h(pb), b1 = lds32h(pb + 8);
                #pragma unroll
                for (int i = 0; i < 2; ++i) mma16816h(acc[i][j], a[i], b0, b1);
            }
        }
        __syncthreads();
    }

    // epilogue: bias + relu
    #pragma unroll
    for (int i = 0; i < 2; ++i) {
        int rows[2] = { bm + wm + i * 16 + g, bm + wm + i * 16 + g + 8 };
        #pragma unroll
        for (int j = 0; j < 8; ++j) {
            int col = bn + wn + j * 8 + 2 * tq;
            float b0 = __ldg(bias + col), b1 = __ldg(bias + col + 1);
            #pragma unroll
            for (int h = 0; h < 2; ++h) {
                int row = rows[h];
                if (row >= N_NODES) continue;
                float ox = fmaxf(acc[i][j][h * 2 + 0] + b0, 0.f);
                float oy = fmaxf(acc[i][j][h * 2 + 1] + b1, 0.f);
                if (OUTSEL == 3) {
                    float2 o = { ox, oy };
                    *(float2*)(g_h3 + (size_t)row * N + col) = o;
                } else {
                    __half* outp = (OUTSEL == 0) ? g_fB : g_fA;
                    __half2 hh = __floats2half2_rn(ox, oy);
                    *(__half2*)(outp + (size_t)row * N + col) = hh;
                }
            }
        }
    }
}

// ---------------- global add pool (segment-based, batch sorted) --------------
#define POOL_SPLIT 8
__global__ void k_zero_out(float* out, int n) {
    int i = blockIdx.x * blockDim.x + threadIdx.x;
    if (i < n) out[i] = 0.f;
}
__global__ void k_pool_seg(float* __restrict__ out) {
    int gph = blockIdx.x;
    int part = blockIdx.y;
    int c = threadIdx.x;             // 128 cols
    int beg = g_gofs[gph], end = g_gofs[gph + 1];
    float s = 0.f;
    for (int i = beg + part; i < end; i += POOL_SPLIT)
        s += g_h3[(size_t)i * 128 + c];
    atomicAdd(&out[gph * 128 + c], s);
}

// ---------------- launch ----------------------------------------------------
extern "C" void kernel_launch(void* const* d_in, const int* in_sizes, int n_in,
                              void* d_out, int out_size) {
    const float* x     = (const float*)d_in[0];
    const int*   ei    = (const int*)d_in[1];     // int32 (JAX x64 disabled)
    const int*   batch = (const int*)d_in[2];
    const float* W1l = (const float*)d_in[3];
    const float* b1  = (const float*)d_in[4];
    const float* W1r = (const float*)d_in[5];
    const float* W2l = (const float*)d_in[6];
    const float* b2  = (const float*)d_in[7];
    const float* W2r = (const float*)d_in[8];
    const float* W3l = (const float*)d_in[9];
    const float* b3  = (const float*)d_in[10];
    const float* W3r = (const float*)d_in[11];
    float* out = (float*)d_out;

    const int EB   = (N_EDGES + 255) / 256;
    const int NBK  = (N_NODES + 255) / 256;
    const int AGGB = (N_NODES * 32 + 255) / 256;

    // preprocessing: counting sort of edges by dst + graph offsets
    k_zero_deg<<<NBK, 256>>>();
    k_count<<<EB, 256>>>(ei);
    k_chunk_sums<<<N_CHUNKS, SCAN_CHUNK>>>();
    k_scan_partials<<<1, 512>>>();
    k_scan_chunks<<<N_CHUNKS, SCAN_CHUNK>>>();
    k_fill<<<EB, 256>>>(ei);
    k_gofs<<<NBK, 256>>>(batch);
    k_convert_x<<<(N_NODES * 32 + 255) / 256, 256>>>(x);

    dim3 gm1((N_NODES + 127) / 128, 2);   // N=256
    dim3 gm3((N_NODES + 127) / 128, 1);   // N=128

    // layer 1: K=128 -> 256   (in g_fA, out g_fB)
    k_convert_w<128, 256><<<(256 * 128 / 4 + 255) / 256, 256>>>(W1l, W1r);
    k_aggregate_f16<2, 0><<<AGGB, 256>>>();
    k_gemm_f16<128, 256, 0, 0><<<gm1, 256, GEMM_SMEM>>>(b1);
    // layer 2: K=256 -> 256   (in g_fB, out g_fA)
    k_convert_w<256, 256><<<(256 * 256 / 4 + 255) / 256, 256>>>(W2l, W2r);
    k_aggregate_f16<4, 1><<<AGGB, 256>>>();
    k_gemm_f16<256, 256, 1, 1><<<gm1, 256, GEMM_SMEM>>>(b2);
    // layer 3: K=256 -> 128   (in g_fA, out g_h3 fp32)
    k_convert_w<256, 128><<<(128 * 256 / 4 + 255) / 256, 256>>>(W3l, W3r);
    k_aggregate_f16<4, 0><<<AGGB, 256>>>();
    k_gemm_f16<256, 128, 0, 3><<<gm3, 256, GEMM_SMEM>>>(b3);

    // global add pool (segment reduction)
    k_zero_out<<<(out_size + 255) / 256, 256>>>(out, out_size);
    dim3 pg(N_GRAPHS, POOL_SPLIT);
    k_pool_seg<<<pg, 128>>>(out);
}

// round 9
// speedup vs baseline: 3.1317x; 1.0972x over previous
#include <cuda_runtime.h>
#include <cuda_fp16.h>
#include <cstdint>

#define N_NODES 50000
#define N_EDGES 1600000
#define N_GRAPHS 64

// ---------------- scratch (device globals; no allocations allowed) ----------
__device__ int   g_deg[N_NODES];
__device__ int   g_off[N_NODES + 1];
__device__ int   g_cursor[N_NODES];
__device__ float g_deginv[N_NODES];
__device__ int   g_srcs[N_EDGES];
__device__ int   g_partials[512];
__device__ int   g_gofs[N_GRAPHS + 1];

__device__ __half g_fA [(size_t)N_NODES * 256];   // feature ping (x, h2)
__device__ __half g_fB [(size_t)N_NODES * 256];   // feature pong (h1, P3)
__device__ __half g_a1h[(size_t)N_NODES * 256];   // aggregated features (fp16)
__device__ __half g_w1l[256 * 128], g_w1r[256 * 128];
__device__ __half g_w2l[256 * 256], g_w2r[256 * 256];
__device__ __half g_w3l[128 * 256], g_w3r[128 * 256];
__device__ float  g_h3 [(size_t)N_NODES * 128];   // Q3 then final h3 (fp32)

#define SCAN_CHUNK 128
#define N_CHUNKS ((N_NODES + SCAN_CHUNK - 1) / SCAN_CHUNK)   // 391

// ---------------- small asm helpers -----------------------------------------
__device__ __forceinline__ uint32_t smem_u32(const void* p) {
    uint32_t r;
    asm("{ .reg .u64 t; cvta.to.shared.u64 t, %1; cvt.u32.u64 %0, t; }" : "=r"(r) : "l"(p));
    return r;
}
__device__ __forceinline__ void cp_async16(uint32_t dst, const void* src, int src_bytes) {
    asm volatile("cp.async.cg.shared.global [%0], [%1], 16, %2;"
                 :: "r"(dst), "l"(src), "r"(src_bytes));
}
__device__ __forceinline__ void cp_commit() {
    asm volatile("cp.async.commit_group;" ::: "memory");
}
template <int NPend>
__device__ __forceinline__ void cp_wait() {
    asm volatile("cp.async.wait_group %0;" :: "n"(NPend) : "memory");
}

// ---------------- preprocessing: counting sort of edges by dst --------------
__global__ void k_zero_deg() {
    int i = blockIdx.x * blockDim.x + threadIdx.x;
    if (i < N_NODES) g_deg[i] = 0;
}
__global__ void k_count(const int* __restrict__ ei) {
    int i = blockIdx.x * blockDim.x + threadIdx.x;
    if (i >= N_EDGES) return;
    atomicAdd(&g_deg[ei[N_EDGES + i]], 1);
}
__global__ void k_chunk_sums() {
    __shared__ int s[SCAN_CHUNK];
    int i = blockIdx.x * SCAN_CHUNK + threadIdx.x;
    s[threadIdx.x] = (i < N_NODES) ? g_deg[i] : 0;
    __syncthreads();
    for (int stride = SCAN_CHUNK / 2; stride > 0; stride >>= 1) {
        if (threadIdx.x < stride) s[threadIdx.x] += s[threadIdx.x + stride];
        __syncthreads();
    }
    if (threadIdx.x == 0) g_partials[blockIdx.x] = s[0];
}
// parallel exclusive scan of the 391 chunk sums (Hillis-Steele over 512 thr)
__global__ void k_scan_partials() {
    __shared__ int s[512];
    int t = threadIdx.x;
    int v = (t < N_CHUNKS) ? g_partials[t] : 0;
    s[t] = v;
    __syncthreads();
    #pragma unroll
    for (int off = 1; off < 512; off <<= 1) {
        int x = (t >= off) ? s[t - off] : 0;
        __syncthreads();
        s[t] += x;
        __syncthreads();
    }
    if (t < N_CHUNKS) g_partials[t] = s[t] - v;   // exclusive
    if (t == 0) g_off[N_NODES] = N_EDGES;
}
// per-chunk exclusive scan via shfl warp scans
__global__ void k_scan_chunks() {
    int i = blockIdx.x * SCAN_CHUNK + threadIdx.x;
    int d = (i < N_NODES) ? g_deg[i] : 0;
    int lane = threadIdx.x & 31, wid = threadIdx.x >> 5;
    __shared__ int ws[4];
    int x = d;
    #pragma unroll
    for (int off = 1; off < 32; off <<= 1) {
        int y = __shfl_up_sync(0xFFFFFFFFu, x, off);
        if (lane >= off) x += y;
    }
    if (lane == 31) ws[wid] = x;
    __syncthreads();
    int add = 0;
    #pragma unroll
    for (int w = 0; w < 4; ++w)
        if (w < wid) add += ws[w];
    int excl = x + add - d;
    if (i < N_NODES) {
        int o = g_partials[blockIdx.x] + excl;
        g_off[i] = o;
        g_cursor[i] = o;
        g_deginv[i] = (d > 0) ? (1.0f / (float)d) : 0.0f;
    }
}
__global__ void k_fill(const int* __restrict__ ei) {
    int i = blockIdx.x * blockDim.x + threadIdx.x;
    if (i >= N_EDGES) return;
    int s = ei[i];
    int d = ei[N_EDGES + i];
    int pos = atomicAdd(&g_cursor[d], 1);
    g_srcs[pos] = s;
}
__global__ void k_gofs(const int* __restrict__ batch) {
    int i = blockIdx.x * blockDim.x + threadIdx.x;
    if (i >= N_NODES) return;
    int b = batch[i];
    if (i == 0) {
        for (int g = 0; g <= b; ++g) g_gofs[g] = 0;
    } else {
        int p = batch[i - 1];
        if (p != b)
            for (int g = p + 1; g <= b; ++g) g_gofs[g] = i;
    }
    if (i == N_NODES - 1)
        for (int g = b + 1; g <= N_GRAPHS; ++g) g_gofs[g] = N_NODES;
}

// ---------------- conversions ------------------------------------------------
__global__ void k_convert_x(const float* __restrict__ x) {
    int idx = blockIdx.x * blockDim.x + threadIdx.x;   // float4 index
    if (idx >= N_NODES * 32) return;
    float4 v = ((const float4*)x)[idx];
    __half2 a = __floats2half2_rn(v.x, v.y);
    __half2 b = __floats2half2_rn(v.z, v.w);
    uint2 pk = { *(uint32_t*)&a, *(uint32_t*)&b };
    *(uint2*)(g_fA + (size_t)idx * 4) = pk;
}
__device__ __forceinline__ void cvt4(const float* src, __half* dst, int idx) {
    float4 v = ((const float4*)src)[idx];
    __half2 a = __floats2half2_rn(v.x, v.y);
    __half2 b = __floats2half2_rn(v.z, v.w);
    uint2 pk = { *(uint32_t*)&a, *(uint32_t*)&b };
    *(uint2*)(dst + (size_t)idx * 4) = pk;
}
// all six weight matrices in one launch (65536 float4 total)
__global__ void k_convert_w(const float* __restrict__ W1l, const float* __restrict__ W1r,
                            const float* __restrict__ W2l, const float* __restrict__ W2r,
                            const float* __restrict__ W3l, const float* __restrict__ W3r) {
    int idx = blockIdx.x * blockDim.x + threadIdx.x;
    const int S1 = 256 * 128 / 4;     // 8192
    const int S2 = 256 * 256 / 4;     // 16384
    const int S3 = 128 * 256 / 4;     // 8192
    if (idx < S1)                 { cvt4(W1l, g_w1l, idx); cvt4(W1r, g_w1r, idx); return; }
    idx -= S1;
    if (idx < S2)                 { cvt4(W2l, g_w2l, idx); cvt4(W2r, g_w2r, idx); return; }
    idx -= S2;
    if (idx < S3)                 { cvt4(W3l, g_w3l, idx); cvt4(W3r, g_w3r, idx); return; }
}

// ---------------- aggregation: warp per node, fp16 gather, fp32 accum -------
// HV: half2 per lane (row dim = HV*64). INSEL: 0 -> g_fA, 1 -> g_fB.
template <int HV, int INSEL>
__device__ __forceinline__ void gather_node(int w, int lane, float2* accv) {
    const __half* base = (INSEL == 0) ? g_fA : g_fB;
    const int RV = HV * 32;
    int beg = g_off[w], end = g_off[w + 1];

    float2 acc0[HV], acc1[HV];
    #pragma unroll
    for (int v = 0; v < HV; ++v) {
        acc0[v] = make_float2(0.f, 0.f);
        acc1[v] = make_float2(0.f, 0.f);
    }
    int j = beg;
    for (; j + 2 <= end; j += 2) {
        int s0 = g_srcs[j], s1 = g_srcs[j + 1];
        const __half* p0 = base + ((size_t)s0 * RV + lane * HV) * 2;
        const __half* p1 = base + ((size_t)s1 * RV + lane * HV) * 2;
        __half2 h0[HV], h1[HV];
        if (HV == 4) {
            uint4 v0 = *(const uint4*)p0;
            uint4 v1 = *(const uint4*)p1;
            h0[0] = *(__half2*)&v0.x; h0[1] = *(__half2*)&v0.y;
            h0[2] = *(__half2*)&v0.z; h0[3] = *(__half2*)&v0.w;
            h1[0] = *(__half2*)&v1.x; h1[1] = *(__half2*)&v1.y;
            h1[2] = *(__half2*)&v1.z; h1[3] = *(__half2*)&v1.w;
        } else {
            uint2 v0 = *(const uint2*)p0;
            uint2 v1 = *(const uint2*)p1;
            h0[0] = *(__half2*)&v0.x; h0[1] = *(__half2*)&v0.y;
            h1[0] = *(__half2*)&v1.x; h1[1] = *(__half2*)&v1.y;
        }
        #pragma unroll
        for (int v = 0; v < HV; ++v) {
            float2 f0 = __half22float2(h0[v]);
            float2 f1 = __half22float2(h1[v]);
            acc0[v].x += f0.x; acc0[v].y += f0.y;
            acc1[v].x += f1.x; acc1[v].y += f1.y;
        }
    }
    if (j < end) {
        int s0 = g_srcs[j];
        const __half* p0 = base + ((size_t)s0 * RV + lane * HV) * 2;
        __half2 h0[HV];
        if (HV == 4) {
            uint4 v0 = *(const uint4*)p0;
            h0[0] = *(__half2*)&v0.x; h0[1] = *(__half2*)&v0.y;
            h0[2] = *(__half2*)&v0.z; h0[3] = *(__half2*)&v0.w;
        } else {
            uint2 v0 = *(const uint2*)p0;
            h0[0] = *(__half2*)&v0.x; h0[1] = *(__half2*)&v0.y;
        }
        #pragma unroll
        for (int v = 0; v < HV; ++v) {
            float2 f0 = __half22float2(h0[v]);
            acc0[v].x += f0.x; acc0[v].y += f0.y;
        }
    }
    #pragma unroll
    for (int v = 0; v < HV; ++v) {
        accv[v].x = acc0[v].x + acc1[v].x;
        accv[v].y = acc0[v].y + acc1[v].y;
    }
}

template <int HV, int INSEL>
__global__ void k_aggregate_f16() {
    int w = (blockIdx.x * blockDim.x + threadIdx.x) >> 5;
    if (w >= N_NODES) return;
    int lane = threadIdx.x & 31;
    float inv = g_deginv[w];
    float2 acc[HV];
    gather_node<HV, INSEL>(w, lane, acc);
    __half* row = g_a1h + (size_t)w * HV * 64;
    #pragma unroll
    for (int v = 0; v < HV; ++v) {
        __half2 r = __floats2half2_rn(acc[v].x * inv, acc[v].y * inv);
        *(__half2*)(row + (lane * HV + v) * 2) = r;
    }
}

// final L3 aggregation: gather P3 (g_fB, 128-d), h3 = relu(agg + Q3 + b3)
__global__ void k_agg_final(const float* __restrict__ bias) {
    int w = (blockIdx.x * blockDim.x + threadIdx.x) >> 5;
    if (w >= N_NODES) return;
    int lane = threadIdx.x & 31;
    float inv = g_deginv[w];
    float2 acc[2];
    gather_node<2, 1>(w, lane, acc);
    float* hrow = g_h3 + (size_t)w * 128;     // holds Q3, overwritten with h3
    #pragma unroll
    for (int v = 0; v < 2; ++v) {
        int c = (lane * 2 + v) * 2;
        float2 q = *(float2*)(hrow + c);
        float2 b = *(const float2*)(bias + c);
        float2 o;
        o.x = fmaxf(acc[v].x * inv + q.x + b.x, 0.f);
        o.y = fmaxf(acc[v].y * inv + q.y + b.y, 0.f);
        *(float2*)(hrow + c) = o;
    }
}

// ---------------- fp16 HMMA GEMM (cp.async pipelined) ------------------------
__device__ __forceinline__ uint32_t lds32h(const __half* p) {
    return *(const uint32_t*)p;
}
__device__ __forceinline__ void mma16816h(float* c, const uint32_t* a, uint32_t b0, uint32_t b1) {
    asm volatile(
        "mma.sync.aligned.m16n8k16.row.col.f32.f16.f16.f32 "
        "{%0,%1,%2,%3}, {%4,%5,%6,%7}, {%8,%9}, {%0,%1,%2,%3};"
        : "+f"(c[0]), "+f"(c[1]), "+f"(c[2]), "+f"(c[3])
        : "r"(a[0]), "r"(a[1]), "r"(a[2]), "r"(a[3]), "r"(b0), "r"(b1));
}

#define GLD 40
#define TILEH (128 * GLD)
#define GEMM_SMEM (2 * 2 * TILEH * 2)   // 40960 bytes

__device__ __forceinline__ void gemm_slab_load(
    const __half* __restrict__ Ap, const __half* __restrict__ Bp,
    int K, int koff, int bm, int bn, int t, int buf, __half* dynsm)
{
    __half* stage = dynsm + (size_t)buf * 2 * TILEH;
    __half* sA = stage;
    __half* sB = stage + TILEH;
    #pragma unroll
    for (int i = 0; i < 2; ++i) {
        int idx = t + i * 256;
        int row = idx >> 2, q = idx & 3;
        int gm = bm + row;
        int ok = (gm < N_NODES) ? 16 : 0;
        int gmc = (gm < N_NODES) ? gm : 0;
        cp_async16(smem_u32(sA + row * GLD + q * 8), Ap + (size_t)gmc * K + koff + q * 8, ok);
        cp_async16(smem_u32(sB + row * GLD + q * 8), Bp + (size_t)(bn + row) * K + koff + q * 8, 16);
    }
    cp_commit();
}

__device__ __forceinline__ void gemm_slab_mma(
    const __half* pA, const __half* pB, int wm, int wn, int g, int tq,
    float acc[2][8][4])
{
    #pragma unroll
    for (int k16 = 0; k16 < 32; k16 += 16) {
        uint32_t a[2][4];
        #pragma unroll
        for (int i = 0; i < 2; ++i) {
            const __half* ph = pA + (wm + i * 16 + g) * GLD + k16 + 2 * tq;
            a[i][0] = lds32h(ph);
            a[i][1] = lds32h(ph + 8 * GLD);
            a[i][2] = lds32h(ph + 8);
            a[i][3] = lds32h(ph + 8 * GLD + 8);
        }
        #pragma unroll
        for (int j = 0; j < 8; ++j) {
            const __half* pb = pB + (wn + j * 8 + g) * GLD + k16 + 2 * tq;
            uint32_t b0 = lds32h(pb), b1 = lds32h(pb + 8);
            #pragma unroll
            for (int i = 0; i < 2; ++i) mma16816h(acc[i][j], a[i], b0, b1);
        }
    }
}

// dual-A GEMM + bias + relu. WSEL: 1 -> (w1l,w1r), 2 -> (w2l,w2r)
// INSEL: A2 (0 g_fA, 1 g_fB); OUTSEL: 0 -> g_fB, 1 -> g_fA
template <int K, int N, int WSEL, int INSEL, int OUTSEL>
__global__ __launch_bounds__(256)
void k_gemm_dual(const float* __restrict__ bias) {
    extern __shared__ __half dynsm[];
    const __half* __restrict__ A1 = g_a1h;
    const __half* __restrict__ A2 = (INSEL == 0) ? g_fA : g_fB;
    const __half* __restrict__ Bl = (WSEL == 1) ? g_w1l : g_w2l;
    const __half* __restrict__ Br = (WSEL == 1) ? g_w1r : g_w2r;

    int t = threadIdx.x;
    int lane = t & 31, wid = t >> 5;
    int wm = (wid & 3) * 32, wn = (wid >> 2) * 64;
    int bm = blockIdx.x * 128, bn = blockIdx.y * 128;
    int g = lane >> 2, tq = lane & 3;

    float acc[2][8][4];
    #pragma unroll
    for (int i = 0; i < 2; ++i)
        #pragma unroll
        for (int j = 0; j < 8; ++j)
            #pragma unroll
            for (int q = 0; q < 4; ++q) acc[i][j][q] = 0.f;

    constexpr int HALF = K / 32;
    constexpr int SLABS = 2 * HALF;

    auto srcA = [&](int s) { return (s < HALF) ? A1 : A2; };
    auto srcB = [&](int s) { return (s < HALF) ? Bl : Br; };
    auto koff = [&](int s) { return ((s < HALF) ? s : s - HALF) * 32; };

    gemm_slab_load(srcA(0), srcB(0), K, koff(0), bm, bn, t, 0, dynsm);
    for (int s = 0; s < SLABS; ++s) {
        if (s + 1 < SLABS) {
            gemm_slab_load(srcA(s + 1), srcB(s + 1), K, koff(s + 1), bm, bn, t, (s + 1) & 1, dynsm);
            cp_wait<1>();
        } else {
            cp_wait<0>();
        }
        __syncthreads();
        const __half* pA = dynsm + (size_t)(s & 1) * 2 * TILEH;
        gemm_slab_mma(pA, pA + TILEH, wm, wn, g, tq, acc);
        __syncthreads();
    }

    #pragma unroll
    for (int i = 0; i < 2; ++i) {
        int rows[2] = { bm + wm + i * 16 + g, bm + wm + i * 16 + g + 8 };
        #pragma unroll
        for (int j = 0; j < 8; ++j) {
            int col = bn + wn + j * 8 + 2 * tq;
            float b0 = __ldg(bias + col), b1 = __ldg(bias + col + 1);
            #pragma unroll
            for (int h = 0; h < 2; ++h) {
                int row = rows[h];
                if (row >= N_NODES) continue;
                float ox = fmaxf(acc[i][j][h * 2 + 0] + b0, 0.f);
                float oy = fmaxf(acc[i][j][h * 2 + 1] + b1, 0.f);
                __half* outp = (OUTSEL == 0) ? g_fB : g_fA;
                __half2 hh = __floats2half2_rn(ox, oy);
                *(__half2*)(outp + (size_t)row * N + col) = hh;
            }
        }
    }
}

// single-A GEMM for L3: A = g_fA (h2, K=256)
// blockIdx.y==0: B=g_w3l -> P3 fp16 to g_fB; ==1: B=g_w3r -> Q3 fp32 to g_h3
__global__ __launch_bounds__(256)
void k_gemm_l3() {
    extern __shared__ __half dynsm[];
    constexpr int K = 256, N = 128;
    const __half* __restrict__ A = g_fA;
    const __half* __restrict__ B = (blockIdx.y == 0) ? g_w3l : g_w3r;

    int t = threadIdx.x;
    int lane = t & 31, wid = t >> 5;
    int wm = (wid & 3) * 32, wn = (wid >> 2) * 64;
    int bm = blockIdx.x * 128;
    int g = lane >> 2, tq = lane & 3;

    float acc[2][8][4];
    #pragma unroll
    for (int i = 0; i < 2; ++i)
        #pragma unroll
        for (int j = 0; j < 8; ++j)
            #pragma unroll
            for (int q = 0; q < 4; ++q) acc[i][j][q] = 0.f;

    constexpr int SLABS = K / 32;   // 8
    gemm_slab_load(A, B, K, 0, bm, 0, t, 0, dynsm);
    for (int s = 0; s < SLABS; ++s) {
        if (s + 1 < SLABS) {
            gemm_slab_load(A, B, K, (s + 1) * 32, bm, 0, t, (s + 1) & 1, dynsm);
            cp_wait<1>();
        } else {
            cp_wait<0>();
        }
        __syncthreads();
        const __half* pA = dynsm + (size_t)(s & 1) * 2 * TILEH;
        gemm_slab_mma(pA, pA + TILEH, wm, wn, g, tq, acc);
        __syncthreads();
    }

    bool q3 = (blockIdx.y == 1);
    #pragma unroll
    for (int i = 0; i < 2; ++i) {
        int rows[2] = { bm + wm + i * 16 + g, bm + wm + i * 16 + g + 8 };
        #pragma unroll
        for (int j = 0; j < 8; ++j) {
            int col = wn + j * 8 + 2 * tq;
            #pragma unroll
            for (int h = 0; h < 2; ++h) {
                int row = rows[h];
                if (row >= N_NODES) continue;
                float ox = acc[i][j][h * 2 + 0];
                float oy = acc[i][j][h * 2 + 1];
                if (q3) {
                    float2 o = { ox, oy };
                    *(float2*)(g_h3 + (size_t)row * N + col) = o;
                } else {
                    __half2 hh = __floats2half2_rn(ox, oy);
                    *(__half2*)(g_fB + (size_t)row * N + col) = hh;
                }
            }
        }
    }
}

// ---------------- global add pool (segment-based, batch sorted) --------------
#define POOL_SPLIT 8
__global__ void k_zero_out(float* out, int n) {
    int i = blockIdx.x * blockDim.x + threadIdx.x;
    if (i < n) out[i] = 0.f;
}
__global__ void k_pool_seg(float* __restrict__ out) {
    int gph = blockIdx.x;
    int part = blockIdx.y;
    int c = threadIdx.x;
    int beg = g_gofs[gph], end = g_gofs[gph + 1];
    float s = 0.f;
    for (int i = beg + part; i < end; i += POOL_SPLIT)
        s += g_h3[(size_t)i * 128 + c];
    atomicAdd(&out[gph * 128 + c], s);
}

// ---------------- launch ----------------------------------------------------
extern "C" void kernel_launch(void* const* d_in, const int* in_sizes, int n_in,
                              void* d_out, int out_size) {
    const float* x     = (const float*)d_in[0];
    const int*   ei    = (const int*)d_in[1];
    const int*   batch = (const int*)d_in[2];
    const float* W1l = (const float*)d_in[3];
    const float* b1  = (const float*)d_in[4];
    const float* W1r = (const float*)d_in[5];
    const float* W2l = (const float*)d_in[6];
    const float* b2  = (const float*)d_in[7];
    const float* W2r = (const float*)d_in[8];
    const float* W3l = (const float*)d_in[9];
    const float* b3  = (const float*)d_in[10];
    const float* W3r = (const float*)d_in[11];
    float* out = (float*)d_out;

    const int EB   = (N_EDGES + 255) / 256;
    const int NBK  = (N_NODES + 255) / 256;
    const int AGGB = (N_NODES * 32 + 255) / 256;

    // preprocessing
    k_zero_deg<<<NBK, 256>>>();
    k_count<<<EB, 256>>>(ei);
    k_chunk_sums<<<N_CHUNKS, SCAN_CHUNK>>>();
    k_scan_partials<<<1, 512>>>();
    k_scan_chunks<<<N_CHUNKS, SCAN_CHUNK>>>();
    k_fill<<<EB, 256>>>(ei);
    k_gofs<<<NBK, 256>>>(batch);
    k_convert_x<<<(N_NODES * 32 + 255) / 256, 256>>>(x);
    k_convert_w<<<(65536 + 255) / 256, 256>>>(W1l, W1r, W2l, W2r, W3l, W3r);

    dim3 gm1((N_NODES + 127) / 128, 2);   // N=256
    dim3 gm3((N_NODES + 127) / 128, 2);   // L3: y -> {P3, Q3}

    // layer 1: K=128 -> 256   (in g_fA, out g_fB)
    k_aggregate_f16<2, 0><<<AGGB, 256>>>();
    k_gemm_dual<128, 256, 1, 0, 0><<<gm1, 256, GEMM_SMEM>>>(b1);
    // layer 2: K=256 -> 256   (in g_fB, out g_fA)
    k_aggregate_f16<4, 1><<<AGGB, 256>>>();
    k_gemm_dual<256, 256, 2, 1, 1><<<gm1, 256, GEMM_SMEM>>>(b2);
    // layer 3 restructured: P3/Q3 GEMM first, then gather P3 (128-d)
    k_gemm_l3<<<gm3, 256, GEMM_SMEM>>>();
    k_agg_final<<<AGGB, 256>>>(b3);

    // global add pool
    k_zero_out<<<(out_size + 255) / 256, 256>>>(out, out_size);
    dim3 pg(N_GRAPHS, POOL_SPLIT);
    k_pool_seg<<<pg, 128>>>(out);
}

// round 10
// speedup vs baseline: 3.2708x; 1.0444x over previous
#include <cuda_runtime.h>
#include <cuda_fp16.h>
#include <cstdint>

#define N_NODES 50000
#define N_EDGES 1600000
#define N_GRAPHS 64

// ---------------- scratch (device globals; no allocations allowed) ----------
__device__ int   g_deg[N_NODES];
__device__ int   g_off[N_NODES + 1];
__device__ int   g_cursor[N_NODES];
__device__ float g_deginv[N_NODES];
__device__ int   g_srcs[N_EDGES];
__device__ int   g_partials[512];
__device__ int   g_gofs[N_GRAPHS + 1];

__device__ __half g_fA [(size_t)N_NODES * 256];   // feature ping (x, h2)
__device__ __half g_fB [(size_t)N_NODES * 256];   // feature pong (h1, P3)
__device__ __half g_a1h[(size_t)N_NODES * 256];   // aggregated features (fp16)
__device__ __half g_w1l[256 * 128], g_w1r[256 * 128];
__device__ __half g_w2l[256 * 256], g_w2r[256 * 256];
__device__ __half g_w3l[128 * 256], g_w3r[128 * 256];
__device__ float  g_h3 [(size_t)N_NODES * 128];   // Q3 then final h3 (fp32)

#define SCAN_CHUNK 128
#define N_CHUNKS ((N_NODES + SCAN_CHUNK - 1) / SCAN_CHUNK)   // 391

// ---------------- small asm helpers -----------------------------------------
__device__ __forceinline__ uint32_t smem_u32(const void* p) {
    uint32_t r;
    asm("{ .reg .u64 t; cvta.to.shared.u64 t, %1; cvt.u32.u64 %0, t; }" : "=r"(r) : "l"(p));
    return r;
}
__device__ __forceinline__ void cp_async16(uint32_t dst, const void* src, int src_bytes) {
    asm volatile("cp.async.cg.shared.global [%0], [%1], 16, %2;"
                 :: "r"(dst), "l"(src), "r"(src_bytes));
}
__device__ __forceinline__ void cp_commit() {
    asm volatile("cp.async.commit_group;" ::: "memory");
}
template <int NPend>
__device__ __forceinline__ void cp_wait() {
    asm volatile("cp.async.wait_group %0;" :: "n"(NPend) : "memory");
}

// ---------------- fused setup: convert_x | zero_deg+gofs | convert_w | zero_out
__device__ __forceinline__ void cvt4(const float* src, __half* dst, int idx) {
    float4 v = ((const float4*)src)[idx];
    __half2 a = __floats2half2_rn(v.x, v.y);
    __half2 b = __floats2half2_rn(v.z, v.w);
    uint2 pk = { *(uint32_t*)&a, *(uint32_t*)&b };
    *(uint2*)(dst + (size_t)idx * 4) = pk;
}
#define SETUP_X   (N_NODES * 32)            // 1,600,000 float4
#define SETUP_N   N_NODES                   // zero_deg + gofs
#define SETUP_W   32768                     // weight float4s
#define SETUP_O   (N_GRAPHS * 128)          // zero out
#define SETUP_TOT (SETUP_X + SETUP_N + SETUP_W + SETUP_O)

__global__ void k_setup(const float* __restrict__ x, const int* __restrict__ batch,
                        const float* __restrict__ W1l, const float* __restrict__ W1r,
                        const float* __restrict__ W2l, const float* __restrict__ W2r,
                        const float* __restrict__ W3l, const float* __restrict__ W3r,
                        float* __restrict__ out) {
    int idx = blockIdx.x * blockDim.x + threadIdx.x;
    if (idx < SETUP_X) { cvt4(x, g_fA, idx); return; }
    idx -= SETUP_X;
    if (idx < SETUP_N) {
        int i = idx;
        g_deg[i] = 0;
        int b = batch[i];
        if (i == 0) {
            for (int g = 0; g <= b; ++g) g_gofs[g] = 0;
        } else {
            int p = batch[i - 1];
            if (p != b)
                for (int g = p + 1; g <= b; ++g) g_gofs[g] = i;
        }
        if (i == N_NODES - 1)
            for (int g = b + 1; g <= N_GRAPHS; ++g) g_gofs[g] = N_NODES;
        return;
    }
    idx -= SETUP_N;
    if (idx < SETUP_W) {
        const int S1 = 256 * 128 / 4;   // 8192
        const int S2 = 256 * 256 / 4;   // 16384
        if (idx < S1)              { cvt4(W1l, g_w1l, idx); cvt4(W1r, g_w1r, idx); return; }
        idx -= S1;
        if (idx < S2)              { cvt4(W2l, g_w2l, idx); cvt4(W2r, g_w2r, idx); return; }
        idx -= S2;
        { cvt4(W3l, g_w3l, idx); cvt4(W3r, g_w3r, idx); return; }
    }
    idx -= SETUP_W;
    if (idx < SETUP_O) out[idx] = 0.f;
}

// ---------------- preprocessing: counting sort of edges by dst --------------
__global__ void k_count(const int* __restrict__ ei) {
    int i = blockIdx.x * blockDim.x + threadIdx.x;
    if (i >= N_EDGES) return;
    atomicAdd(&g_deg[ei[N_EDGES + i]], 1);
}
__global__ void k_chunk_sums() {
    __shared__ int s[SCAN_CHUNK];
    int i = blockIdx.x * SCAN_CHUNK + threadIdx.x;
    s[threadIdx.x] = (i < N_NODES) ? g_deg[i] : 0;
    __syncthreads();
    for (int stride = SCAN_CHUNK / 2; stride > 0; stride >>= 1) {
        if (threadIdx.x < stride) s[threadIdx.x] += s[threadIdx.x + stride];
        __syncthreads();
    }
    if (threadIdx.x == 0) g_partials[blockIdx.x] = s[0];
}
__global__ void k_scan_partials() {
    __shared__ int s[512];
    int t = threadIdx.x;
    int v = (t < N_CHUNKS) ? g_partials[t] : 0;
    s[t] = v;
    __syncthreads();
    #pragma unroll
    for (int off = 1; off < 512; off <<= 1) {
        int x = (t >= off) ? s[t - off] : 0;
        __syncthreads();
        s[t] += x;
        __syncthreads();
    }
    if (t < N_CHUNKS) g_partials[t] = s[t] - v;   // exclusive
    if (t == 0) g_off[N_NODES] = N_EDGES;
}
__global__ void k_scan_chunks() {
    int i = blockIdx.x * SCAN_CHUNK + threadIdx.x;
    int d = (i < N_NODES) ? g_deg[i] : 0;
    int lane = threadIdx.x & 31, wid = threadIdx.x >> 5;
    __shared__ int ws[4];
    int x = d;
    #pragma unroll
    for (int off = 1; off < 32; off <<= 1) {
        int y = __shfl_up_sync(0xFFFFFFFFu, x, off);
        if (lane >= off) x += y;
    }
    if (lane == 31) ws[wid] = x;
    __syncthreads();
    int add = 0;
    #pragma unroll
    for (int w = 0; w < 4; ++w)
        if (w < wid) add += ws[w];
    int excl = x + add - d;
    if (i < N_NODES) {
        int o = g_partials[blockIdx.x] + excl;
        g_off[i] = o;
        g_cursor[i] = o;
        g_deginv[i] = (d > 0) ? (1.0f / (float)d) : 0.0f;
    }
}
__global__ void k_fill(const int* __restrict__ ei) {
    int i = blockIdx.x * blockDim.x + threadIdx.x;
    if (i >= N_EDGES) return;
    int s = ei[i];
    int d = ei[N_EDGES + i];
    int pos = atomicAdd(&g_cursor[d], 1);
    g_srcs[pos] = s;
}

// ---------------- aggregation: warp per node, fp16 gather, fp32 accum -------
template <int HV, int INSEL>
__device__ __forceinline__ void gather_node(int w, int lane, float2* accv) {
    const __half* base = (INSEL == 0) ? g_fA : g_fB;
    const int RV = HV * 32;
    int beg = g_off[w], end = g_off[w + 1];

    float2 acc0[HV], acc1[HV];
    #pragma unroll
    for (int v = 0; v < HV; ++v) {
        acc0[v] = make_float2(0.f, 0.f);
        acc1[v] = make_float2(0.f, 0.f);
    }
    int j = beg;
    for (; j + 2 <= end; j += 2) {
        int s0 = g_srcs[j], s1 = g_srcs[j + 1];
        const __half* p0 = base + ((size_t)s0 * RV + lane * HV) * 2;
        const __half* p1 = base + ((size_t)s1 * RV + lane * HV) * 2;
        __half2 h0[HV], h1[HV];
        if (HV == 4) {
            uint4 v0 = *(const uint4*)p0;
            uint4 v1 = *(const uint4*)p1;
            h0[0] = *(__half2*)&v0.x; h0[1] = *(__half2*)&v0.y;
            h0[2] = *(__half2*)&v0.z; h0[3] = *(__half2*)&v0.w;
            h1[0] = *(__half2*)&v1.x; h1[1] = *(__half2*)&v1.y;
            h1[2] = *(__half2*)&v1.z; h1[3] = *(__half2*)&v1.w;
        } else {
            uint2 v0 = *(const uint2*)p0;
            uint2 v1 = *(const uint2*)p1;
            h0[0] = *(__half2*)&v0.x; h0[1] = *(__half2*)&v0.y;
            h1[0] = *(__half2*)&v1.x; h1[1] = *(__half2*)&v1.y;
        }
        #pragma unroll
        for (int v = 0; v < HV; ++v) {
            float2 f0 = __half22float2(h0[v]);
            float2 f1 = __half22float2(h1[v]);
            acc0[v].x += f0.x; acc0[v].y += f0.y;
            acc1[v].x += f1.x; acc1[v].y += f1.y;
        }
    }
    if (j < end) {
        int s0 = g_srcs[j];
        const __half* p0 = base + ((size_t)s0 * RV + lane * HV) * 2;
        __half2 h0[HV];
        if (HV == 4) {
            uint4 v0 = *(const uint4*)p0;
            h0[0] = *(__half2*)&v0.x; h0[1] = *(__half2*)&v0.y;
            h0[2] = *(__half2*)&v0.z; h0[3] = *(__half2*)&v0.w;
        } else {
            uint2 v0 = *(const uint2*)p0;
            h0[0] = *(__half2*)&v0.x; h0[1] = *(__half2*)&v0.y;
        }
        #pragma unroll
        for (int v = 0; v < HV; ++v) {
            float2 f0 = __half22float2(h0[v]);
            acc0[v].x += f0.x; acc0[v].y += f0.y;
        }
    }
    #pragma unroll
    for (int v = 0; v < HV; ++v) {
        accv[v].x = acc0[v].x + acc1[v].x;
        accv[v].y = acc0[v].y + acc1[v].y;
    }
}

template <int HV, int INSEL>
__global__ void k_aggregate_f16() {
    int w = (blockIdx.x * blockDim.x + threadIdx.x) >> 5;
    if (w >= N_NODES) return;
    int lane = threadIdx.x & 31;
    float inv = g_deginv[w];
    float2 acc[HV];
    gather_node<HV, INSEL>(w, lane, acc);
    __half* row = g_a1h + (size_t)w * HV * 64;
    #pragma unroll
    for (int v = 0; v < HV; ++v) {
        __half2 r = __floats2half2_rn(acc[v].x * inv, acc[v].y * inv);
        *(__half2*)(row + (lane * HV + v) * 2) = r;
    }
}

// final L3 aggregation: gather P3 (g_fB, 128-d), h3 = relu(agg + Q3 + b3)
__global__ void k_agg_final(const float* __restrict__ bias) {
    int w = (blockIdx.x * blockDim.x + threadIdx.x) >> 5;
    if (w >= N_NODES) return;
    int lane = threadIdx.x & 31;
    float inv = g_deginv[w];
    float2 acc[2];
    gather_node<2, 1>(w, lane, acc);
    float* hrow = g_h3 + (size_t)w * 128;
    #pragma unroll
    for (int v = 0; v < 2; ++v) {
        int c = (lane * 2 + v) * 2;
        float2 q = *(float2*)(hrow + c);
        float2 b = *(const float2*)(bias + c);
        float2 o;
        o.x = fmaxf(acc[v].x * inv + q.x + b.x, 0.f);
        o.y = fmaxf(acc[v].y * inv + q.y + b.y, 0.f);
        *(float2*)(hrow + c) = o;
    }
}

// ---------------- fp16 HMMA GEMM (3-stage cp.async pipeline) -----------------
__device__ __forceinline__ uint32_t lds32h(const __half* p) {
    return *(const uint32_t*)p;
}
__device__ __forceinline__ void mma16816h(float* c, const uint32_t* a, uint32_t b0, uint32_t b1) {
    asm volatile(
        "mma.sync.aligned.m16n8k16.row.col.f32.f16.f16.f32 "
        "{%0,%1,%2,%3}, {%4,%5,%6,%7}, {%8,%9}, {%0,%1,%2,%3};"
        : "+f"(c[0]), "+f"(c[1]), "+f"(c[2]), "+f"(c[3])
        : "r"(a[0]), "r"(a[1]), "r"(a[2]), "r"(a[3]), "r"(b0), "r"(b1));
}

#define GLD 40
#define TILEH (128 * GLD)
#define STAGES 3
#define GEMM_SMEM (STAGES * 2 * TILEH * 2)   // 61440 bytes

__device__ __forceinline__ void gemm_slab_load(
    const __half* __restrict__ Ap, const __half* __restrict__ Bp,
    int K, int koff, int bm, int bn, int t, int buf, __half* dynsm)
{
    __half* stage = dynsm + (size_t)buf * 2 * TILEH;
    __half* sA = stage;
    __half* sB = stage + TILEH;
    #pragma unroll
    for (int i = 0; i < 2; ++i) {
        int idx = t + i * 256;
        int row = idx >> 2, q = idx & 3;
        int gm = bm + row;
        int ok = (gm < N_NODES) ? 16 : 0;
        int gmc = (gm < N_NODES) ? gm : 0;
        cp_async16(smem_u32(sA + row * GLD + q * 8), Ap + (size_t)gmc * K + koff + q * 8, ok);
        cp_async16(smem_u32(sB + row * GLD + q * 8), Bp + (size_t)(bn + row) * K + koff + q * 8, 16);
    }
    cp_commit();
}

__device__ __forceinline__ void gemm_slab_mma(
    const __half* pA, const __half* pB, int wm, int wn, int g, int tq,
    float acc[2][8][4])
{
    #pragma unroll
    for (int k16 = 0; k16 < 32; k16 += 16) {
        uint32_t a[2][4];
        #pragma unroll
        for (int i = 0; i < 2; ++i) {
            const __half* ph = pA + (wm + i * 16 + g) * GLD + k16 + 2 * tq;
            a[i][0] = lds32h(ph);
            a[i][1] = lds32h(ph + 8 * GLD);
            a[i][2] = lds32h(ph + 8);
            a[i][3] = lds32h(ph + 8 * GLD + 8);
        }
        #pragma unroll
        for (int j = 0; j < 8; ++j) {
            const __half* pb = pB + (wn + j * 8 + g) * GLD + k16 + 2 * tq;
            uint32_t b0 = lds32h(pb), b1 = lds32h(pb + 8);
            #pragma unroll
            for (int i = 0; i < 2; ++i) mma16816h(acc[i][j], a[i], b0, b1);
        }
    }
}

// dual-A GEMM + bias + relu. WSEL: 1 -> (w1l,w1r), 2 -> (w2l,w2r)
// INSEL: A2 (0 g_fA, 1 g_fB); OUTSEL: 0 -> g_fB, 1 -> g_fA
template <int K, int N, int WSEL, int INSEL, int OUTSEL>
__global__ __launch_bounds__(256, 2)
void k_gemm_dual(const float* __restrict__ bias) {
    extern __shared__ __half dynsm[];
    const __half* __restrict__ A1 = g_a1h;
    const __half* __restrict__ A2 = (INSEL == 0) ? g_fA : g_fB;
    const __half* __restrict__ Bl = (WSEL == 1) ? g_w1l : g_w2l;
    const __half* __restrict__ Br = (WSEL == 1) ? g_w1r : g_w2r;

    int t = threadIdx.x;
    int lane = t & 31, wid = t >> 5;
    int wm = (wid & 3) * 32, wn = (wid >> 2) * 64;
    int bm = blockIdx.x * 128, bn = blockIdx.y * 128;
    int g = lane >> 2, tq = lane & 3;

    float acc[2][8][4];
    #pragma unroll
    for (int i = 0; i < 2; ++i)
        #pragma unroll
        for (int j = 0; j < 8; ++j)
            #pragma unroll
            for (int q = 0; q < 4; ++q) acc[i][j][q] = 0.f;

    constexpr int HALF = K / 32;
    constexpr int SLABS = 2 * HALF;

    auto srcA = [&](int s) { return (s < HALF) ? A1 : A2; };
    auto srcB = [&](int s) { return (s < HALF) ? Bl : Br; };
    auto koff = [&](int s) { return ((s < HALF) ? s : s - HALF) * 32; };

    gemm_slab_load(srcA(0), srcB(0), K, koff(0), bm, bn, t, 0, dynsm);
    gemm_slab_load(srcA(1), srcB(1), K, koff(1), bm, bn, t, 1, dynsm);
    for (int s = 0; s < SLABS; ++s) {
        cp_wait<1>();
        __syncthreads();
        if (s + 2 < SLABS)
            gemm_slab_load(srcA(s + 2), srcB(s + 2), K, koff(s + 2), bm, bn, t, (s + 2) % STAGES, dynsm);
        else
            cp_commit();   // keep pending-group count uniform
        const __half* pA = dynsm + (size_t)(s % STAGES) * 2 * TILEH;
        gemm_slab_mma(pA, pA + TILEH, wm, wn, g, tq, acc);
    }

    #pragma unroll
    for (int i = 0; i < 2; ++i) {
        int rows[2] = { bm + wm + i * 16 + g, bm + wm + i * 16 + g + 8 };
        #pragma unroll
        for (int j = 0; j < 8; ++j) {
            int col = bn + wn + j * 8 + 2 * tq;
            float b0 = __ldg(bias + col), b1 = __ldg(bias + col + 1);
            #pragma unroll
            for (int h = 0; h < 2; ++h) {
                int row = rows[h];
                if (row >= N_NODES) continue;
                float ox = fmaxf(acc[i][j][h * 2 + 0] + b0, 0.f);
                float oy = fmaxf(acc[i][j][h * 2 + 1] + b1, 0.f);
                __half* outp = (OUTSEL == 0) ? g_fB : g_fA;
                __half2 hh = __floats2half2_rn(ox, oy);
                *(__half2*)(outp + (size_t)row * N + col) = hh;
            }
        }
    }
}

// single-A GEMM for L3: A = g_fA (h2, K=256)
// blockIdx.y==0: B=g_w3l -> P3 fp16 to g_fB; ==1: B=g_w3r -> Q3 fp32 to g_h3
__global__ __launch_bounds__(256, 2)
void k_gemm_l3() {
    extern __shared__ __half dynsm[];
    constexpr int K = 256, N = 128;
    const __half* __restrict__ A = g_fA;
    const __half* __restrict__ B = (blockIdx.y == 0) ? g_w3l : g_w3r;

    int t = threadIdx.x;
    int lane = t & 31, wid = t >> 5;
    int wm = (wid & 3) * 32, wn = (wid >> 2) * 64;
    int bm = blockIdx.x * 128;
    int g = lane >> 2, tq = lane & 3;

    float acc[2][8][4];
    #pragma unroll
    for (int i = 0; i < 2; ++i)
        #pragma unroll
        for (int j = 0; j < 8; ++j)
            #pragma unroll
            for (int q = 0; q < 4; ++q) acc[i][j][q] = 0.f;

    constexpr int SLABS = K / 32;   // 8
    gemm_slab_load(A, B, K, 0, bm, 0, t, 0, dynsm);
    gemm_slab_load(A, B, K, 32, bm, 0, t, 1, dynsm);
    for (int s = 0; s < SLABS; ++s) {
        cp_wait<1>();
        __syncthreads();
        if (s + 2 < SLABS)
            gemm_slab_load(A, B, K, (s + 2) * 32, bm, 0, t, (s + 2) % STAGES, dynsm);
        else
            cp_commit();
        const __half* pA = dynsm + (size_t)(s % STAGES) * 2 * TILEH;
        gemm_slab_mma(pA, pA + TILEH, wm, wn, g, tq, acc);
    }

    bool q3 = (blockIdx.y == 1);
    #pragma unroll
    for (int i = 0; i < 2; ++i) {
        int rows[2] = { bm + wm + i * 16 + g, bm + wm + i * 16 + g + 8 };
        #pragma unroll
        for (int j = 0; j < 8; ++j) {
            int col = wn + j * 8 + 2 * tq;
            #pragma unroll
            for (int h = 0; h < 2; ++h) {
                int row = rows[h];
                if (row >= N_NODES) continue;
                float ox = acc[i][j][h * 2 + 0];
                float oy = acc[i][j][h * 2 + 1];
                if (q3) {
                    float2 o = { ox, oy };
                    *(float2*)(g_h3 + (size_t)row * N + col) = o;
                } else {
                    __half2 hh = __floats2half2_rn(ox, oy);
                    *(__half2*)(g_fB + (size_t)row * N + col) = hh;
                }
            }
        }
    }
}

// ---------------- global add pool (segment-based, batch sorted) --------------
#define POOL_SPLIT 8
__global__ void k_pool_seg(float* __restrict__ out) {
    int gph = blockIdx.x;
    int part = blockIdx.y;
    int c = threadIdx.x;
    int beg = g_gofs[gph], end = g_gofs[gph + 1];
    float s = 0.f;
    for (int i = beg + part; i < end; i += POOL_SPLIT)
        s += g_h3[(size_t)i * 128 + c];
    atomicAdd(&out[gph * 128 + c], s);
}

// ---------------- launch ----------------------------------------------------
extern "C" void kernel_launch(void* const* d_in, const int* in_sizes, int n_in,
                              void* d_out, int out_size) {
    const float* x     = (const float*)d_in[0];
    const int*   ei    = (const int*)d_in[1];
    const int*   batch = (const int*)d_in[2];
    const float* W1l = (const float*)d_in[3];
    const float* b1  = (const float*)d_in[4];
    const float* W1r = (const float*)d_in[5];
    const float* W2l = (const float*)d_in[6];
    const float* b2  = (const float*)d_in[7];
    const float* W2r = (const float*)d_in[8];
    const float* W3l = (const float*)d_in[9];
    const float* b3  = (const float*)d_in[10];
    const float* W3r = (const float*)d_in[11];
    float* out = (float*)d_out;

    const int EB   = (N_EDGES + 255) / 256;
    const int AGGB = (N_NODES * 32 + 255) / 256;

    cudaFuncSetAttribute(k_gemm_dual<128, 256, 1, 0, 0>, cudaFuncAttributeMaxDynamicSharedMemorySize, GEMM_SMEM);
    cudaFuncSetAttribute(k_gemm_dual<256, 256, 2, 1, 1>, cudaFuncAttributeMaxDynamicSharedMemorySize, GEMM_SMEM);
    cudaFuncSetAttribute(k_gemm_l3, cudaFuncAttributeMaxDynamicSharedMemorySize, GEMM_SMEM);

    // fused setup + preprocessing
    k_setup<<<(SETUP_TOT + 255) / 256, 256>>>(x, batch, W1l, W1r, W2l, W2r, W3l, W3r, out);
    k_count<<<EB, 256>>>(ei);
    k_chunk_sums<<<N_CHUNKS, SCAN_CHUNK>>>();
    k_scan_partials<<<1, 512>>>();
    k_scan_chunks<<<N_CHUNKS, SCAN_CHUNK>>>();
    k_fill<<<EB, 256>>>(ei);

    dim3 gm1((N_NODES + 127) / 128, 2);   // N=256
    dim3 gm3((N_NODES + 127) / 128, 2);   // L3: y -> {P3, Q3}

    // layer 1: K=128 -> 256   (in g_fA, out g_fB)
    k_aggregate_f16<2, 0><<<AGGB, 256>>>();
    k_gemm_dual<128, 256, 1, 0, 0><<<gm1, 256, GEMM_SMEM>>>(b1);
    // layer 2: K=256 -> 256   (in g_fB, out g_fA)
    k_aggregate_f16<4, 1><<<AGGB, 256>>>();
    k_gemm_dual<256, 256, 2, 1, 1><<<gm1, 256, GEMM_SMEM>>>(b2);
    // layer 3 restructured: P3/Q3 GEMM first, then gather P3 (128-d)
    k_gemm_l3<<<gm3, 256, GEMM_SMEM>>>();
    k_agg_final<<<AGGB, 256>>>(b3);

    // global add pool (out zeroed in k_setup)
    dim3 pg(N_GRAPHS, POOL_SPLIT);
    k_pool_seg<<<pg, 128>>>(out);
}

// round 11
// speedup vs baseline: 3.3180x; 1.0144x over previous
#include <cuda_runtime.h>
#include <cuda_fp16.h>
#include <cstdint>

#define N_NODES 50000
#define N_EDGES 1600000
#define N_GRAPHS 64

// ---------------- scratch (device globals; no allocations allowed) ----------
__device__ int   g_deg[N_NODES];
__device__ int   g_off[N_NODES + 1];
__device__ int   g_cursor[N_NODES];
__device__ float g_deginv[N_NODES];
__device__ int   g_srcs[N_EDGES];
__device__ int   g_partials[512];
__device__ int   g_gofs[N_GRAPHS + 1];

__device__ __half g_fA [(size_t)N_NODES * 256];   // feature ping (x, h2)
__device__ __half g_fB [(size_t)N_NODES * 256];   // feature pong (h1, P3)
__device__ __half g_a1h[(size_t)N_NODES * 256];   // aggregated features (fp16)
__device__ __half g_w1l[256 * 128], g_w1r[256 * 128];
__device__ __half g_w2l[256 * 256], g_w2r[256 * 256];
__device__ __half g_w3l[128 * 256], g_w3r[128 * 256];
__device__ float  g_h3 [(size_t)N_NODES * 128];   // Q3 then final h3 (fp32)

#define SCAN_CHUNK 128
#define N_CHUNKS ((N_NODES + SCAN_CHUNK - 1) / SCAN_CHUNK)   // 391

// ---------------- small asm helpers -----------------------------------------
__device__ __forceinline__ uint32_t smem_u32(const void* p) {
    uint32_t r;
    asm("{ .reg .u64 t; cvta.to.shared.u64 t, %1; cvt.u32.u64 %0, t; }" : "=r"(r) : "l"(p));
    return r;
}
__device__ __forceinline__ void cp_async16(uint32_t dst, const void* src, int src_bytes) {
    asm volatile("cp.async.cg.shared.global [%0], [%1], 16, %2;"
                 :: "r"(dst), "l"(src), "r"(src_bytes));
}
__device__ __forceinline__ void cp_commit() {
    asm volatile("cp.async.commit_group;" ::: "memory");
}
template <int NPend>
__device__ __forceinline__ void cp_wait() {
    asm volatile("cp.async.wait_group %0;" :: "n"(NPend) : "memory");
}
__device__ __forceinline__ void ldsm_x4(uint32_t addr, uint32_t& r0, uint32_t& r1,
                                        uint32_t& r2, uint32_t& r3) {
    asm volatile("ldmatrix.sync.aligned.m8n8.x4.shared.b16 {%0,%1,%2,%3}, [%4];"
                 : "=r"(r0), "=r"(r1), "=r"(r2), "=r"(r3) : "r"(addr));
}

// ---------------- fused setup: convert_x | zero_deg+gofs | convert_w | zero_out
__device__ __forceinline__ void cvt4(const float* src, __half* dst, int idx) {
    float4 v = ((const float4*)src)[idx];
    __half2 a = __floats2half2_rn(v.x, v.y);
    __half2 b = __floats2half2_rn(v.z, v.w);
    uint2 pk = { *(uint32_t*)&a, *(uint32_t*)&b };
    *(uint2*)(dst + (size_t)idx * 4) = pk;
}
#define SETUP_X   (N_NODES * 32)
#define SETUP_N   N_NODES
#define SETUP_W   32768
#define SETUP_O   (N_GRAPHS * 128)
#define SETUP_TOT (SETUP_X + SETUP_N + SETUP_W + SETUP_O)

__global__ void k_setup(const float* __restrict__ x, const int* __restrict__ batch,
                        const float* __restrict__ W1l, const float* __restrict__ W1r,
                        const float* __restrict__ W2l, const float* __restrict__ W2r,
                        const float* __restrict__ W3l, const float* __restrict__ W3r,
                        float* __restrict__ out) {
    int idx = blockIdx.x * blockDim.x + threadIdx.x;
    if (idx < SETUP_X) { cvt4(x, g_fA, idx); return; }
    idx -= SETUP_X;
    if (idx < SETUP_N) {
        int i = idx;
        g_deg[i] = 0;
        int b = batch[i];
        if (i == 0) {
            for (int g = 0; g <= b; ++g) g_gofs[g] = 0;
        } else {
            int p = batch[i - 1];
            if (p != b)
                for (int g = p + 1; g <= b; ++g) g_gofs[g] = i;
        }
        if (i == N_NODES - 1)
            for (int g = b + 1; g <= N_GRAPHS; ++g) g_gofs[g] = N_NODES;
        return;
    }
    idx -= SETUP_N;
    if (idx < SETUP_W) {
        const int S1 = 256 * 128 / 4;
        const int S2 = 256 * 256 / 4;
        if (idx < S1)              { cvt4(W1l, g_w1l, idx); cvt4(W1r, g_w1r, idx); return; }
        idx -= S1;
        if (idx < S2)              { cvt4(W2l, g_w2l, idx); cvt4(W2r, g_w2r, idx); return; }
        idx -= S2;
        { cvt4(W3l, g_w3l, idx); cvt4(W3r, g_w3r, idx); return; }
    }
    idx -= SETUP_W;
    if (idx < SETUP_O) out[idx] = 0.f;
}

// ---------------- preprocessing: counting sort of edges by dst --------------
__global__ void k_count(const int* __restrict__ ei) {
    int i = blockIdx.x * blockDim.x + threadIdx.x;
    if (i >= N_EDGES) return;
    atomicAdd(&g_deg[ei[N_EDGES + i]], 1);
}
__global__ void k_chunk_sums() {
    __shared__ int s[SCAN_CHUNK];
    int i = blockIdx.x * SCAN_CHUNK + threadIdx.x;
    s[threadIdx.x] = (i < N_NODES) ? g_deg[i] : 0;
    __syncthreads();
    for (int stride = SCAN_CHUNK / 2; stride > 0; stride >>= 1) {
        if (threadIdx.x < stride) s[threadIdx.x] += s[threadIdx.x + stride];
        __syncthreads();
    }
    if (threadIdx.x == 0) g_partials[blockIdx.x] = s[0];
}
__global__ void k_scan_partials() {
    __shared__ int s[512];
    int t = threadIdx.x;
    int v = (t < N_CHUNKS) ? g_partials[t] : 0;
    s[t] = v;
    __syncthreads();
    #pragma unroll
    for (int off = 1; off < 512; off <<= 1) {
        int x = (t >= off) ? s[t - off] : 0;
        __syncthreads();
        s[t] += x;
        __syncthreads();
    }
    if (t < N_CHUNKS) g_partials[t] = s[t] - v;   // exclusive
    if (t == 0) g_off[N_NODES] = N_EDGES;
}
__global__ void k_scan_chunks() {
    int i = blockIdx.x * SCAN_CHUNK + threadIdx.x;
    int d = (i < N_NODES) ? g_deg[i] : 0;
    int lane = threadIdx.x & 31, wid = threadIdx.x >> 5;
    __shared__ int ws[4];
    int x = d;
    #pragma unroll
    for (int off = 1; off < 32; off <<= 1) {
        int y = __shfl_up_sync(0xFFFFFFFFu, x, off);
        if (lane >= off) x += y;
    }
    if (lane == 31) ws[wid] = x;
    __syncthreads();
    int add = 0;
    #pragma unroll
    for (int w = 0; w < 4; ++w)
        if (w < wid) add += ws[w];
    int excl = x + add - d;
    if (i < N_NODES) {
        int o = g_partials[blockIdx.x] + excl;
        g_off[i] = o;
        g_cursor[i] = o;
        g_deginv[i] = (d > 0) ? (1.0f / (float)d) : 0.0f;
    }
}
__global__ void k_fill(const int* __restrict__ ei) {
    int i = blockIdx.x * blockDim.x + threadIdx.x;
    if (i >= N_EDGES) return;
    int s = ei[i];
    int d = ei[N_EDGES + i];
    int pos = atomicAdd(&g_cursor[d], 1);
    g_srcs[pos] = s;
}

// ---------------- aggregation: warp per node, fp16 gather, fp32 accum -------
template <int HV, int INSEL>
__device__ __forceinline__ void gather_node(int w, int lane, float2* accv) {
    const __half* base = (INSEL == 0) ? g_fA : g_fB;
    const int RV = HV * 32;
    int beg = g_off[w], end = g_off[w + 1];

    float2 acc0[HV], acc1[HV];
    #pragma unroll
    for (int v = 0; v < HV; ++v) {
        acc0[v] = make_float2(0.f, 0.f);
        acc1[v] = make_float2(0.f, 0.f);
    }
    int j = beg;
    for (; j + 2 <= end; j += 2) {
        int s0 = g_srcs[j], s1 = g_srcs[j + 1];
        const __half* p0 = base + ((size_t)s0 * RV + lane * HV) * 2;
        const __half* p1 = base + ((size_t)s1 * RV + lane * HV) * 2;
        __half2 h0[HV], h1[HV];
        if (HV == 4) {
            uint4 v0 = *(const uint4*)p0;
            uint4 v1 = *(const uint4*)p1;
            h0[0] = *(__half2*)&v0.x; h0[1] = *(__half2*)&v0.y;
            h0[2] = *(__half2*)&v0.z; h0[3] = *(__half2*)&v0.w;
            h1[0] = *(__half2*)&v1.x; h1[1] = *(__half2*)&v1.y;
            h1[2] = *(__half2*)&v1.z; h1[3] = *(__half2*)&v1.w;
        } else {
            uint2 v0 = *(const uint2*)p0;
            uint2 v1 = *(const uint2*)p1;
            h0[0] = *(__half2*)&v0.x; h0[1] = *(__half2*)&v0.y;
            h1[0] = *(__half2*)&v1.x; h1[1] = *(__half2*)&v1.y;
        }
        #pragma unroll
        for (int v = 0; v < HV; ++v) {
            float2 f0 = __half22float2(h0[v]);
            float2 f1 = __half22float2(h1[v]);
            acc0[v].x += f0.x; acc0[v].y += f0.y;
            acc1[v].x += f1.x; acc1[v].y += f1.y;
        }
    }
    if (j < end) {
        int s0 = g_srcs[j];
        const __half* p0 = base + ((size_t)s0 * RV + lane * HV) * 2;
        __half2 h0[HV];
        if (HV == 4) {
            uint4 v0 = *(const uint4*)p0;
            h0[0] = *(__half2*)&v0.x; h0[1] = *(__half2*)&v0.y;
            h0[2] = *(__half2*)&v0.z; h0[3] = *(__half2*)&v0.w;
        } else {
            uint2 v0 = *(const uint2*)p0;
            h0[0] = *(__half2*)&v0.x; h0[1] = *(__half2*)&v0.y;
        }
        #pragma unroll
        for (int v = 0; v < HV; ++v) {
            float2 f0 = __half22float2(h0[v]);
            acc0[v].x += f0.x; acc0[v].y += f0.y;
        }
    }
    #pragma unroll
    for (int v = 0; v < HV; ++v) {
        accv[v].x = acc0[v].x + acc1[v].x;
        accv[v].y = acc0[v].y + acc1[v].y;
    }
}

template <int HV, int INSEL>
__global__ void k_aggregate_f16() {
    int w = (blockIdx.x * blockDim.x + threadIdx.x) >> 5;
    if (w >= N_NODES) return;
    int lane = threadIdx.x & 31;
    float inv = g_deginv[w];
    float2 acc[HV];
    gather_node<HV, INSEL>(w, lane, acc);
    __half* row = g_a1h + (size_t)w * HV * 64;
    #pragma unroll
    for (int v = 0; v < HV; ++v) {
        __half2 r = __floats2half2_rn(acc[v].x * inv, acc[v].y * inv);
        *(__half2*)(row + (lane * HV + v) * 2) = r;
    }
}

// final L3 aggregation: gather P3 (g_fB, 128-d), h3 = relu(agg + Q3 + b3)
__global__ void k_agg_final(const float* __restrict__ bias) {
    int w = (blockIdx.x * blockDim.x + threadIdx.x) >> 5;
    if (w >= N_NODES) return;
    int lane = threadIdx.x & 31;
    float inv = g_deginv[w];
    float2 acc[2];
    gather_node<2, 1>(w, lane, acc);
    float* hrow = g_h3 + (size_t)w * 128;
    #pragma unroll
    for (int v = 0; v < 2; ++v) {
        int c = (lane * 2 + v) * 2;
        float2 q = *(float2*)(hrow + c);
        float2 b = *(const float2*)(bias + c);
        float2 o;
        o.x = fmaxf(acc[v].x * inv + q.x + b.x, 0.f);
        o.y = fmaxf(acc[v].y * inv + q.y + b.y, 0.f);
        *(float2*)(hrow + c) = o;
    }
}

// ---------------- fp16 HMMA GEMM (3-stage cp.async + ldmatrix) ---------------
__device__ __forceinline__ void mma16816h(float* c, const uint32_t* a, uint32_t b0, uint32_t b1) {
    asm volatile(
        "mma.sync.aligned.m16n8k16.row.col.f32.f16.f16.f32 "
        "{%0,%1,%2,%3}, {%4,%5,%6,%7}, {%8,%9}, {%0,%1,%2,%3};"
        : "+f"(c[0]), "+f"(c[1]), "+f"(c[2]), "+f"(c[3])
        : "r"(a[0]), "r"(a[1]), "r"(a[2]), "r"(a[3]), "r"(b0), "r"(b1));
}

#define GLD 40
#define TILEH (128 * GLD)
#define STAGES 3
#define GEMM_SMEM (STAGES * 2 * TILEH * 2)   // 61440 bytes

__device__ __forceinline__ void gemm_slab_load(
    const __half* __restrict__ Ap, const __half* __restrict__ Bp,
    int K, int koff, int bm, int bn, int t, int buf, __half* dynsm)
{
    __half* stage = dynsm + (size_t)buf * 2 * TILEH;
    __half* sA = stage;
    __half* sB = stage + TILEH;
    #pragma unroll
    for (int i = 0; i < 2; ++i) {
        int idx = t + i * 256;
        int row = idx >> 2, q = idx & 3;
        int gm = bm + row;
        int ok = (gm < N_NODES) ? 16 : 0;
        int gmc = (gm < N_NODES) ? gm : 0;
        cp_async16(smem_u32(sA + row * GLD + q * 8), Ap + (size_t)gmc * K + koff + q * 8, ok);
        cp_async16(smem_u32(sB + row * GLD + q * 8), Bp + (size_t)(bn + row) * K + koff + q * 8, 16);
    }
    cp_commit();
}

// ldmatrix-based mainloop: 6 LDSM per k16 (2 A, 4 B) feeding 16 HMMA
__device__ __forceinline__ void gemm_slab_mma(
    const __half* pA, const __half* pB, int wm, int wn, int lane,
    float acc[2][8][4])
{
    int la = lane & 15, ha = lane >> 4;           // A: row sel / k-half sel
    int lb = lane & 7;
    int nb = (lane >> 4) & 1, kb = (lane >> 3) & 1;   // B: n-half / k-half
    #pragma unroll
    for (int k16 = 0; k16 < 32; k16 += 16) {
        uint32_t a[2][4];
        #pragma unroll
        for (int i = 0; i < 2; ++i) {
            uint32_t addr = smem_u32(pA + (wm + i * 16 + la) * GLD + k16 + ha * 8);
            ldsm_x4(addr, a[i][0], a[i][1], a[i][2], a[i][3]);
        }
        #pragma unroll
        for (int jp = 0; jp < 4; ++jp) {
            uint32_t b0j, b1j, b0k, b1k;
            uint32_t addr = smem_u32(pB + (wn + jp * 16 + lb + nb * 8) * GLD + k16 + kb * 8);
            ldsm_x4(addr, b0j, b1j, b0k, b1k);
            #pragma unroll
            for (int i = 0; i < 2; ++i) mma16816h(acc[i][2 * jp],     a[i], b0j, b1j);
            #pragma unroll
            for (int i = 0; i < 2; ++i) mma16816h(acc[i][2 * jp + 1], a[i], b0k, b1k);
        }
    }
}

// dual-A GEMM + bias + relu. WSEL: 1 -> (w1l,w1r), 2 -> (w2l,w2r)
template <int K, int N, int WSEL, int INSEL, int OUTSEL>
__global__ __launch_bounds__(256, 2)
void k_gemm_dual(const float* __restrict__ bias) {
    extern __shared__ __half dynsm[];
    const __half* __restrict__ A1 = g_a1h;
    const __half* __restrict__ A2 = (INSEL == 0) ? g_fA : g_fB;
    const __half* __restrict__ Bl = (WSEL == 1) ? g_w1l : g_w2l;
    const __half* __restrict__ Br = (WSEL == 1) ? g_w1r : g_w2r;

    int t = threadIdx.x;
    int lane = t & 31, wid = t >> 5;
    int wm = (wid & 3) * 32, wn = (wid >> 2) * 64;
    int bm = blockIdx.x * 128, bn = blockIdx.y * 128;
    int g = lane >> 2, tq = lane & 3;

    float acc[2][8][4];
    #pragma unroll
    for (int i = 0; i < 2; ++i)
        #pragma unroll
        for (int j = 0; j < 8; ++j)
            #pragma unroll
            for (int q = 0; q < 4; ++q) acc[i][j][q] = 0.f;

    constexpr int HALF = K / 32;
    constexpr int SLABS = 2 * HALF;

    auto srcA = [&](int s) { return (s < HALF) ? A1 : A2; };
    auto srcB = [&](int s) { return (s < HALF) ? Bl : Br; };
    auto koff = [&](int s) { return ((s < HALF) ? s : s - HALF) * 32; };

    gemm_slab_load(srcA(0), srcB(0), K, koff(0), bm, bn, t, 0, dynsm);
    gemm_slab_load(srcA(1), srcB(1), K, koff(1), bm, bn, t, 1, dynsm);
    for (int s = 0; s < SLABS; ++s) {
        cp_wait<1>();
        __syncthreads();
        if (s + 2 < SLABS)
            gemm_slab_load(srcA(s + 2), srcB(s + 2), K, koff(s + 2), bm, bn, t, (s + 2) % STAGES, dynsm);
        else
            cp_commit();
        const __half* pA = dynsm + (size_t)(s % STAGES) * 2 * TILEH;
        gemm_slab_mma(pA, pA + TILEH, wm, wn, lane, acc);
    }

    #pragma unroll
    for (int i = 0; i < 2; ++i) {
        int rows[2] = { bm + wm + i * 16 + g, bm + wm + i * 16 + g + 8 };
        #pragma unroll
        for (int j = 0; j < 8; ++j) {
            int col = bn + wn + j * 8 + 2 * tq;
            float b0 = __ldg(bias + col), b1 = __ldg(bias + col + 1);
            #pragma unroll
            for (int h = 0; h < 2; ++h) {
                int row = rows[h];
                if (row >= N_NODES) continue;
                float ox = fmaxf(acc[i][j][h * 2 + 0] + b0, 0.f);
                float oy = fmaxf(acc[i][j][h * 2 + 1] + b1, 0.f);
                __half* outp = (OUTSEL == 0) ? g_fB : g_fA;
                __half2 hh = __floats2half2_rn(ox, oy);
                *(__half2*)(outp + (size_t)row * N + col) = hh;
            }
        }
    }
}

// single-A GEMM for L3: A = g_fA (h2, K=256)
__global__ __launch_bounds__(256, 2)
void k_gemm_l3() {
    extern __shared__ __half dynsm[];
    constexpr int K = 256, N = 128;
    const __half* __restrict__ A = g_fA;
    const __half* __restrict__ B = (blockIdx.y == 0) ? g_w3l : g_w3r;

    int t = threadIdx.x;
    int lane = t & 31, wid = t >> 5;
    int wm = (wid & 3) * 32, wn = (wid >> 2) * 64;
    int bm = blockIdx.x * 128;
    int g = lane >> 2, tq = lane & 3;

    float acc[2][8][4];
    #pragma unroll
    for (int i = 0; i < 2; ++i)
        #pragma unroll
        for (int j = 0; j < 8; ++j)
            #pragma unroll
            for (int q = 0; q < 4; ++q) acc[i][j][q] = 0.f;

    constexpr int SLABS = K / 32;
    gemm_slab_load(A, B, K, 0, bm, 0, t, 0, dynsm);
    gemm_slab_load(A, B, K, 32, bm, 0, t, 1, dynsm);
    for (int s = 0; s < SLABS; ++s) {
        cp_wait<1>();
        __syncthreads();
        if (s + 2 < SLABS)
            gemm_slab_load(A, B, K, (s + 2) * 32, bm, 0, t, (s + 2) % STAGES, dynsm);
        else
            cp_commit();
        const __half* pA = dynsm + (size_t)(s % STAGES) * 2 * TILEH;
        gemm_slab_mma(pA, pA + TILEH, wm, wn, lane, acc);
    }

    bool q3 = (blockIdx.y == 1);
    #pragma unroll
    for (int i = 0; i < 2; ++i) {
        int rows[2] = { bm + wm + i * 16 + g, bm + wm + i * 16 + g + 8 };
        #pragma unroll
        for (int j = 0; j < 8; ++j) {
            int col = wn + j * 8 + 2 * tq;
            #pragma unroll
            for (int h = 0; h < 2; ++h) {
                int row = rows[h];
                if (row >= N_NODES) continue;
                float ox = acc[i][j][h * 2 + 0];
                float oy = acc[i][j][h * 2 + 1];
                if (q3) {
                    float2 o = { ox, oy };
                    *(float2*)(g_h3 + (size_t)row * N + col) = o;
                } else {
                    __half2 hh = __floats2half2_rn(ox, oy);
                    *(__half2*)(g_fB + (size_t)row * N + col) = hh;
                }
            }
        }
    }
}

// ---------------- global add pool (segment-based, batch sorted) --------------
#define POOL_SPLIT 8
__global__ void k_pool_seg(float* __restrict__ out) {
    int gph = blockIdx.x;
    int part = blockIdx.y;
    int c = threadIdx.x;
    int beg = g_gofs[gph], end = g_gofs[gph + 1];
    float s = 0.f;
    for (int i = beg + part; i < end; i += POOL_SPLIT)
        s += g_h3[(size_t)i * 128 + c];
    atomicAdd(&out[gph * 128 + c], s);
}

// ---------------- launch ----------------------------------------------------
extern "C" void kernel_launch(void* const* d_in, const int* in_sizes, int n_in,
                              void* d_out, int out_size) {
    const float* x     = (const float*)d_in[0];
    const int*   ei    = (const int*)d_in[1];
    const int*   batch = (const int*)d_in[2];
    const float* W1l = (const float*)d_in[3];
    const float* b1  = (const float*)d_in[4];
    const float* W1r = (const float*)d_in[5];
    const float* W2l = (const float*)d_in[6];
    const float* b2  = (const float*)d_in[7];
    const float* W2r = (const float*)d_in[8];
    const float* W3l = (const float*)d_in[9];
    const float* b3  = (const float*)d_in[10];
    const float* W3r = (const float*)d_in[11];
    float* out = (float*)d_out;

    const int EB   = (N_EDGES + 255) / 256;
    const int AGGB = (N_NODES * 32 + 255) / 256;

    cudaFuncSetAttribute(k_gemm_dual<128, 256, 1, 0, 0>, cudaFuncAttributeMaxDynamicSharedMemorySize, GEMM_SMEM);
    cudaFuncSetAttribute(k_gemm_dual<256, 256, 2, 1, 1>, cudaFuncAttributeMaxDynamicSharedMemorySize, GEMM_SMEM);
    cudaFuncSetAttribute(k_gemm_l3, cudaFuncAttributeMaxDynamicSharedMemorySize, GEMM_SMEM);

    // fused setup + preprocessing
    k_setup<<<(SETUP_TOT + 255) / 256, 256>>>(x, batch, W1l, W1r, W2l, W2r, W3l, W3r, out);
    k_count<<<EB, 256>>>(ei);
    k_chunk_sums<<<N_CHUNKS, SCAN_CHUNK>>>();
    k_scan_partials<<<1, 512>>>();
    k_scan_chunks<<<N_CHUNKS, SCAN_CHUNK>>>();
    k_fill<<<EB, 256>>>(ei);

    dim3 gm1((N_NODES + 127) / 128, 2);   // N=256
    dim3 gm3((N_NODES + 127) / 128, 2);   // L3: y -> {P3, Q3}

    // layer 1: K=128 -> 256   (in g_fA, out g_fB)
    k_aggregate_f16<2, 0><<<AGGB, 256>>>();
    k_gemm_dual<128, 256, 1, 0, 0><<<gm1, 256, GEMM_SMEM>>>(b1);
    // layer 2: K=256 -> 256   (in g_fB, out g_fA)
    k_aggregate_f16<4, 1><<<AGGB, 256>>>();
    k_gemm_dual<256, 256, 2, 1, 1><<<gm1, 256, GEMM_SMEM>>>(b2);
    // layer 3 restructured: P3/Q3 GEMM first, then gather P3 (128-d)
    k_gemm_l3<<<gm3, 256, GEMM_SMEM>>>();
    k_agg_final<<<AGGB, 256>>>(b3);

    // global add pool (out zeroed in k_setup)
    dim3 pg(N_GRAPHS, POOL_SPLIT);
    k_pool_seg<<<pg, 128>>>(out);
}